// round 2
// baseline (speedup 1.0000x reference)
#include <cuda_runtime.h>
#include <math.h>

#define BB 2
#define LL 1024
#define DD 1024
#define EE 2048
#define SS 16
#define RR 64
#define NLAYER 4
#define VV 32000
#define MROWS (BB*LL)
#define NCHUNK 16
#define CLEN (LL/NCHUNK)
#define DBCW 96

// ------------------- scratch (static device globals, no allocs) -------------
__device__ float g_h[MROWS*DD];
__device__ float g_xn[MROWS*DD];
__device__ float g_uz[MROWS*2*EE];
__device__ float g_u[MROWS*EE];
__device__ float g_dbc[MROWS*DBCW];
__device__ float g_delta[MROWS*EE];
__device__ float g_y[MROWS*EE];
__device__ float g_gate[MROWS*EE];
__device__ float g_P[NCHUNK*BB*EE*SS];
__device__ float g_hend[NCHUNK*BB*EE*SS];
__device__ float g_h0c[NCHUNK*BB*EE*SS];
__device__ float g_wbar[DD];

__device__ __forceinline__ float siluf(float x) { return x / (1.f + __expf(-x)); }
__device__ __forceinline__ float softplusf(float x) {
    return (x > 20.f) ? x : log1pf(__expf(x));
}

// ------------------- embed ------------------------------------------------
__global__ void k_embed(const int* __restrict__ x, const float* __restrict__ mask,
                        const float* __restrict__ emb) {
    int idx = blockIdx.x * 256 + threadIdx.x;
    if (idx >= MROWS * DD) return;
    int row = idx >> 10;
    int d = idx & 1023;
    g_h[idx] = emb[(size_t)x[row] * DD + d] * mask[row];
}

// ------------------- rmsnorm ----------------------------------------------
__global__ void k_rmsnorm(const float* __restrict__ w) {
    int row = blockIdx.x;
    const float* hr = g_h + (size_t)row * DD;
    float ss = 0.f;
    for (int d = threadIdx.x; d < DD; d += 256) { float v = hr[d]; ss += v * v; }
    __shared__ float red[256];
    red[threadIdx.x] = ss; __syncthreads();
    for (int st = 128; st > 0; st >>= 1) {
        if (threadIdx.x < st) red[threadIdx.x] += red[threadIdx.x + st];
        __syncthreads();
    }
    float scale = rsqrtf(red[0] / DD + 1e-5f);
    for (int d = threadIdx.x; d < DD; d += 256)
        g_xn[(size_t)row * DD + d] = hr[d] * scale * w[d];
}

// ------------------- SGEMM: C(M,N) = A(M,K) @ B(K,N) ----------------------
// mode 0: C = AB ; mode 1: C += AB ; mode 2: C = softplus(AB + bias[col])
__global__ __launch_bounds__(256) void sgemm(
    const float* __restrict__ A, int lda,
    const float* __restrict__ Bp, int ldb,
    float* __restrict__ C, int ldc,
    int M, int N, int Kd,
    const float* __restrict__ bias, int mode)
{
    __shared__ float As[8][128];
    __shared__ float Bs[8][128];
    int tid = threadIdx.x;
    int bm = blockIdx.y * 128, bn = blockIdx.x * 128;
    int tx = tid & 15, ty = tid >> 4;

    float acc[8][8];
    #pragma unroll
    for (int i = 0; i < 8; i++)
        #pragma unroll
        for (int j = 0; j < 8; j++) acc[i][j] = 0.f;

    int ar = tid >> 1;
    int ac = (tid & 1) * 4;
    int br = tid >> 5;
    int bc = (tid & 31) * 4;

    for (int k0 = 0; k0 < Kd; k0 += 8) {
        #pragma unroll
        for (int i = 0; i < 4; i++) {
            int r = bm + ar;
            As[ac + i][ar] = (r < M) ? A[(size_t)r * lda + (k0 + ac + i)] : 0.f;
        }
        #pragma unroll
        for (int i = 0; i < 4; i++) {
            int c = bn + bc + i;
            Bs[br][bc + i] = (c < N) ? Bp[(size_t)(k0 + br) * ldb + c] : 0.f;
        }
        __syncthreads();
        #pragma unroll
        for (int k = 0; k < 8; k++) {
            float ra[8], rb[8];
            float4 a0 = *(const float4*)&As[k][ty * 8];
            float4 a1 = *(const float4*)&As[k][ty * 8 + 4];
            float4 b0 = *(const float4*)&Bs[k][tx * 8];
            float4 b1 = *(const float4*)&Bs[k][tx * 8 + 4];
            ra[0]=a0.x; ra[1]=a0.y; ra[2]=a0.z; ra[3]=a0.w;
            ra[4]=a1.x; ra[5]=a1.y; ra[6]=a1.z; ra[7]=a1.w;
            rb[0]=b0.x; rb[1]=b0.y; rb[2]=b0.z; rb[3]=b0.w;
            rb[4]=b1.x; rb[5]=b1.y; rb[6]=b1.z; rb[7]=b1.w;
            #pragma unroll
            for (int i = 0; i < 8; i++)
                #pragma unroll
                for (int j = 0; j < 8; j++)
                    acc[i][j] = fmaf(ra[i], rb[j], acc[i][j]);
        }
        __syncthreads();
    }

    #pragma unroll
    for (int i = 0; i < 8; i++) {
        int r = bm + ty * 8 + i;
        if (r >= M) continue;
        #pragma unroll
        for (int j = 0; j < 8; j++) {
            int c = bn + tx * 8 + j;
            if (c >= N) continue;
            float v = acc[i][j];
            if (mode == 1) v += C[(size_t)r * ldc + c];
            else if (mode == 2) v = softplusf(v + bias[c]);
            C[(size_t)r * ldc + c] = v;
        }
    }
}

// ------------------- causal depthwise conv + silu -------------------------
__global__ void k_conv(const float* __restrict__ cw, const float* __restrict__ cb) {
    int idx = blockIdx.x * 256 + threadIdx.x;
    if (idx >= MROWS * EE) return;
    int row = idx >> 11;
    int e = idx & (EE - 1);
    int b = row >> 10;
    int l = row & 1023;
    float acc = cb[e];
    #pragma unroll
    for (int k = 0; k < 4; k++) {
        int l2 = l - 3 + k;
        if (l2 >= 0)
            acc += g_uz[(size_t)(b * LL + l2) * (2 * EE) + e] * cw[e * 4 + k];
    }
    g_u[idx] = siluf(acc);
}

// ------------------- selective scan, 3-pass chunked -----------------------
__global__ void k_scanA(const float* __restrict__ A_log_l) {
    int c = blockIdx.x, eg = blockIdx.y, b = blockIdx.z;
    int e = eg * 128 + threadIdx.x;
    __shared__ float sBC[CLEN * 32];
    for (int i = threadIdx.x; i < CLEN * 32; i += 128) {
        int tl = i >> 5, j = i & 31;
        sBC[i] = g_dbc[(size_t)(b * LL + c * CLEN + tl) * DBCW + RR + j];
    }
    __syncthreads();
    float Aa[SS], h[SS], P[SS];
    #pragma unroll
    for (int s = 0; s < SS; s++) {
        Aa[s] = -__expf(A_log_l[e * SS + s]);
        h[s] = 0.f; P[s] = 1.f;
    }
    int rowbase = b * LL + c * CLEN;
    for (int tl = 0; tl < CLEN; tl++) {
        size_t off = (size_t)(rowbase + tl) * EE + e;
        float dv = g_delta[off];
        float du = dv * g_u[off];
        #pragma unroll
        for (int s = 0; s < SS; s++) {
            float dA = __expf(dv * Aa[s]);
            h[s] = fmaf(dA, h[s], du * sBC[tl * 32 + s]);
            P[s] *= dA;
        }
    }
    size_t base = ((size_t)c * BB * EE + b * EE + e) * SS;
    float4* Pp = (float4*)(g_P + base);
    float4* Hp = (float4*)(g_hend + base);
    #pragma unroll
    for (int q = 0; q < 4; q++) {
        Pp[q] = make_float4(P[q*4], P[q*4+1], P[q*4+2], P[q*4+3]);
        Hp[q] = make_float4(h[q*4], h[q*4+1], h[q*4+2], h[q*4+3]);
    }
}

__global__ void k_scanB() {
    int idx = blockIdx.x * 256 + threadIdx.x;
    if (idx >= BB * EE) return;
    float h[SS];
    #pragma unroll
    for (int s = 0; s < SS; s++) h[s] = 0.f;
    for (int c = 0; c < NCHUNK; c++) {
        size_t base = ((size_t)c * BB * EE + idx) * SS;
        float4* H0 = (float4*)(g_h0c + base);
        const float4* Pp = (const float4*)(g_P + base);
        const float4* He = (const float4*)(g_hend + base);
        #pragma unroll
        for (int q = 0; q < 4; q++) {
            H0[q] = make_float4(h[q*4], h[q*4+1], h[q*4+2], h[q*4+3]);
            float4 p = Pp[q], he = He[q];
            h[q*4+0] = fmaf(p.x, h[q*4+0], he.x);
            h[q*4+1] = fmaf(p.y, h[q*4+1], he.y);
            h[q*4+2] = fmaf(p.z, h[q*4+2], he.z);
            h[q*4+3] = fmaf(p.w, h[q*4+3], he.w);
        }
    }
}

__global__ void k_scanC(const float* __restrict__ A_log_l, const float* __restrict__ Dsk) {
    int c = blockIdx.x, eg = blockIdx.y, b = blockIdx.z;
    int e = eg * 128 + threadIdx.x;
    __shared__ float sBC[CLEN * 32];
    for (int i = threadIdx.x; i < CLEN * 32; i += 128) {
        int tl = i >> 5, j = i & 31;
        sBC[i] = g_dbc[(size_t)(b * LL + c * CLEN + tl) * DBCW + RR + j];
    }
    __syncthreads();
    float Aa[SS], h[SS];
    #pragma unroll
    for (int s = 0; s < SS; s++) Aa[s] = -__expf(A_log_l[e * SS + s]);
    size_t base = ((size_t)c * BB * EE + b * EE + e) * SS;
    #pragma unroll
    for (int q = 0; q < 4; q++) {
        float4 v = ((const float4*)(g_h0c + base))[q];
        h[q*4+0] = v.x; h[q*4+1] = v.y; h[q*4+2] = v.z; h[q*4+3] = v.w;
    }
    float dsk = Dsk[e];
    int rowbase = b * LL + c * CLEN;
    for (int tl = 0; tl < CLEN; tl++) {
        size_t off = (size_t)(rowbase + tl) * EE + e;
        float dv = g_delta[off];
        float uv = g_u[off];
        float du = dv * uv;
        float y = 0.f;
        #pragma unroll
        for (int s = 0; s < SS; s++) {
            float dA = __expf(dv * Aa[s]);
            h[s] = fmaf(dA, h[s], du * sBC[tl * 32 + s]);
            y = fmaf(h[s], sBC[tl * 32 + 16 + s], y);
        }
        g_y[off] = y + uv * dsk;
    }
}

// ------------------- gate: y * silu(z) ------------------------------------
__global__ void k_gate() {
    int idx = blockIdx.x * 256 + threadIdx.x;
    if (idx >= MROWS * EE) return;
    int row = idx >> 11;
    int e = idx & (EE - 1);
    float z = g_uz[(size_t)row * (2 * EE) + EE + e];
    g_gate[idx] = g_y[idx] * siluf(z);
}

// ------------------- rw scaling -------------------------------------------
__global__ void k_wbar(const float* __restrict__ W_rw_l) {
    int d = blockIdx.x * 256 + threadIdx.x;
    if (d >= DD) return;
    float s = 0.f;
    #pragma unroll
    for (int j = 0; j < SS; j++) s += W_rw_l[d * SS + j];
    g_wbar[d] = s * (1.f / SS);
}

__global__ void k_rw(const float* __restrict__ b_rw_l) {
    int row = blockIdx.x;
    float* hr = g_h + (size_t)row * DD;
    float dot = 0.f;
    for (int d = threadIdx.x; d < DD; d += 256) dot += hr[d] * g_wbar[d];
    __shared__ float red[256];
    red[threadIdx.x] = dot; __syncthreads();
    for (int st = 128; st > 0; st >>= 1) {
        if (threadIdx.x < st) red[threadIdx.x] += red[threadIdx.x + st];
        __syncthreads();
    }
    float bb = 0.f;
    #pragma unroll
    for (int s = 0; s < SS; s++) bb += b_rw_l[s];
    float scale = red[0] + bb * (1.f / SS);
    for (int d = threadIdx.x; d < DD; d += 256) hr[d] *= scale;
}

// ------------------- final layernorm --------------------------------------
__global__ void k_layernorm(const float* __restrict__ gam, const float* __restrict__ bet) {
    int row = blockIdx.x;
    const float* hr = g_h + (size_t)row * DD;
    __shared__ float red[256];
    float s = 0.f;
    for (int d = threadIdx.x; d < DD; d += 256) s += hr[d];
    red[threadIdx.x] = s; __syncthreads();
    for (int st = 128; st > 0; st >>= 1) {
        if (threadIdx.x < st) red[threadIdx.x] += red[threadIdx.x + st];
        __syncthreads();
    }
    float mu = red[0] / DD;
    __syncthreads();
    float v = 0.f;
    for (int d = threadIdx.x; d < DD; d += 256) { float t = hr[d] - mu; v += t * t; }
    red[threadIdx.x] = v; __syncthreads();
    for (int st = 128; st > 0; st >>= 1) {
        if (threadIdx.x < st) red[threadIdx.x] += red[threadIdx.x + st];
        __syncthreads();
    }
    float inv = rsqrtf(red[0] / DD + 1e-5f);
    for (int d = threadIdx.x; d < DD; d += 256)
        g_xn[(size_t)row * DD + d] = (hr[d] - mu) * inv * gam[d] + bet[d];
}

// ------------------- launch -----------------------------------------------
extern "C" void kernel_launch(void* const* d_in, const int* in_sizes, int n_in,
                              void* d_out, int out_size) {
    const int*   x      = (const int*)d_in[0];
    const float* mask   = (const float*)d_in[1];
    const float* emb    = (const float*)d_in[2];
    const float* norm_w = (const float*)d_in[3];
    const float* W_in   = (const float*)d_in[4];
    const float* conv_w = (const float*)d_in[5];
    const float* conv_b = (const float*)d_in[6];
    const float* W_x    = (const float*)d_in[7];
    const float* W_dt   = (const float*)d_in[8];
    const float* b_dt   = (const float*)d_in[9];
    const float* A_log  = (const float*)d_in[10];
    const float* D_skip = (const float*)d_in[11];
    const float* W_out  = (const float*)d_in[12];
    const float* W_rw   = (const float*)d_in[13];
    const float* b_rw   = (const float*)d_in[14];
    const float* ln_g   = (const float*)d_in[15];
    const float* ln_b   = (const float*)d_in[16];
    const float* head_W = (const float*)d_in[17];
    float* out = (float*)d_out;

    float *ph, *pxn, *puz, *pu, *pdbc, *pdelta, *pgate;
    cudaGetSymbolAddress((void**)&ph,     g_h);
    cudaGetSymbolAddress((void**)&pxn,    g_xn);
    cudaGetSymbolAddress((void**)&puz,    g_uz);
    cudaGetSymbolAddress((void**)&pu,     g_u);
    cudaGetSymbolAddress((void**)&pdbc,   g_dbc);
    cudaGetSymbolAddress((void**)&pdelta, g_delta);
    cudaGetSymbolAddress((void**)&pgate,  g_gate);

    k_embed<<<(MROWS * DD + 255) / 256, 256>>>(x, mask, emb);

    for (int l = 0; l < NLAYER; l++) {
        k_rmsnorm<<<MROWS, 256>>>(norm_w + l * DD);

        // uz = xn @ W_in   (2048x1024 @ 1024x4096)
        sgemm<<<dim3(2 * EE / 128, MROWS / 128), 256>>>(
            pxn, DD, W_in + (size_t)l * DD * 2 * EE, 2 * EE,
            puz, 2 * EE, MROWS, 2 * EE, DD, nullptr, 0);

        k_conv<<<(MROWS * EE + 255) / 256, 256>>>(conv_w + l * EE * 4, conv_b + l * EE);

        // dbc = u @ W_x   (2048x2048 @ 2048x96)
        sgemm<<<dim3((DBCW + 127) / 128, MROWS / 128), 256>>>(
            pu, EE, W_x + (size_t)l * EE * DBCW, DBCW,
            pdbc, DBCW, MROWS, DBCW, EE, nullptr, 0);

        // delta = softplus(dr @ W_dt + b_dt)  (2048x64 @ 64x2048)
        sgemm<<<dim3(EE / 128, MROWS / 128), 256>>>(
            pdbc, DBCW, W_dt + (size_t)l * RR * EE, EE,
            pdelta, EE, MROWS, EE, RR, b_dt + l * EE, 2);

        k_scanA<<<dim3(NCHUNK, EE / 128, BB), 128>>>(A_log + (size_t)l * EE * SS);
        k_scanB<<<(BB * EE + 255) / 256, 256>>>();
        k_scanC<<<dim3(NCHUNK, EE / 128, BB), 128>>>(A_log + (size_t)l * EE * SS,
                                                     D_skip + l * EE);

        k_gate<<<(MROWS * EE + 255) / 256, 256>>>();

        // h += gate @ W_out  (2048x2048 @ 2048x1024)
        sgemm<<<dim3(DD / 128, MROWS / 128), 256>>>(
            pgate, EE, W_out + (size_t)l * EE * DD, DD,
            ph, DD, MROWS, DD, EE, nullptr, 1);

        k_wbar<<<(DD + 255) / 256, 256>>>(W_rw + (size_t)l * DD * SS);
        k_rw<<<MROWS, 256>>>(b_rw + l * SS);
    }

    k_layernorm<<<MROWS, 256>>>(ln_g, ln_b);

    // logits = xn @ head_W  (2048x1024 @ 1024x32000)
    sgemm<<<dim3((VV + 127) / 128, MROWS / 128), 256>>>(
        pxn, DD, head_W, VV, out, VV, MROWS, VV, DD, nullptr, 0);
}

// round 4
// speedup vs baseline: 1.3181x; 1.3181x over previous
#include <cuda_runtime.h>
#include <math.h>
#include <stdint.h>

#define BB 2
#define LL 1024
#define DD 1024
#define EE 2048
#define SS 16
#define RR 64
#define NLAYER 4
#define VV 32000
#define MROWS (BB*LL)
#define NCHUNK 16
#define CLEN (LL/NCHUNK)
#define DBCW 96

// ------------------- scratch (static device globals, no allocs) -------------
__device__ float g_h[MROWS*DD];
__device__ float g_xn[MROWS*DD];
__device__ float g_uz[MROWS*2*EE];
__device__ float g_u[MROWS*EE];
__device__ float g_dbc[MROWS*DBCW];
__device__ float g_delta[MROWS*EE];
__device__ float g_y[MROWS*EE];
__device__ float g_gate[MROWS*EE];
__device__ float g_P[NCHUNK*BB*EE*SS];
__device__ float g_hend[NCHUNK*BB*EE*SS];
__device__ float g_h0c[NCHUNK*BB*EE*SS];
__device__ float g_wbar[DD];

__device__ __forceinline__ float siluf(float x) { return x / (1.f + __expf(-x)); }
__device__ __forceinline__ float softplusf(float x) {
    return (x > 20.f) ? x : log1pf(__expf(x));
}
__device__ __forceinline__ uint32_t f2tf32(float x) {
    uint32_t r; asm("cvt.rna.tf32.f32 %0, %1;" : "=r"(r) : "f"(x)); return r;
}

// ------------------- embed ------------------------------------------------
__global__ void k_embed(const int* __restrict__ x, const float* __restrict__ mask,
                        const float* __restrict__ emb) {
    int idx = blockIdx.x * 256 + threadIdx.x;
    if (idx >= MROWS * DD) return;
    int row = idx >> 10;
    int d = idx & 1023;
    g_h[idx] = emb[(size_t)x[row] * DD + d] * mask[row];
}

// ------------------- rmsnorm ----------------------------------------------
__global__ void k_rmsnorm(const float* __restrict__ w) {
    int row = blockIdx.x;
    const float* hr = g_h + (size_t)row * DD;
    float ss = 0.f;
    for (int d = threadIdx.x; d < DD; d += 256) { float v = hr[d]; ss += v * v; }
    __shared__ float red[256];
    red[threadIdx.x] = ss; __syncthreads();
    for (int st = 128; st > 0; st >>= 1) {
        if (threadIdx.x < st) red[threadIdx.x] += red[threadIdx.x + st];
        __syncthreads();
    }
    float scale = rsqrtf(red[0] / DD + 1e-5f);
    for (int d = threadIdx.x; d < DD; d += 256)
        g_xn[(size_t)row * DD + d] = hr[d] * scale * w[d];
}

// ------------------- TF32 tensor-core GEMM --------------------------------
// C(M,N) = A(M,K) @ B(K,N); A,B row-major fp32.
// PASSES: 1 = plain tf32; 3 = hi*hi + hi*lo + lo*hi (fp32-grade accuracy)
// MODE:   0 = store; 1 = C += AB; 2 = C = softplus(AB + bias[col])
#define MMA8(d, a, b) \
    asm volatile("mma.sync.aligned.m16n8k8.row.col.f32.tf32.tf32.f32 " \
                 "{%0,%1,%2,%3},{%4,%5,%6,%7},{%8,%9},{%0,%1,%2,%3};" \
                 : "+f"(d[0]), "+f"(d[1]), "+f"(d[2]), "+f"(d[3]) \
                 : "r"(a[0]), "r"(a[1]), "r"(a[2]), "r"(a[3]), \
                   "r"(b[0]), "r"(b[1]))

template<int PASSES, int MODE>
__global__ __launch_bounds__(256, 1) void tgemm(
    const float* __restrict__ A, int lda,
    const float* __restrict__ Bp, int ldb,
    float* __restrict__ C, int ldc,
    int M, int N, int K,
    const float* __restrict__ bias)
{
    __shared__ uint32_t As[2][16][132];
    __shared__ uint32_t Bs[2][16][132];

    int tid = threadIdx.x;
    int lane = tid & 31;
    int warp = tid >> 5;
    int wm = warp & 1;      // 2 warps along M (64 rows each)
    int wn = warp >> 1;     // 4 warps along N (32 cols each)
    int bm = blockIdx.y * 128;
    int bn = blockIdx.x * 128;
    int lr = lane >> 2;     // 0..7
    int lc = lane & 3;      // 0..3

    float acc[4][4][4];
    #pragma unroll
    for (int i = 0; i < 4; i++)
        #pragma unroll
        for (int j = 0; j < 4; j++)
            #pragma unroll
            for (int q = 0; q < 4; q++) acc[i][j][q] = 0.f;

    for (int k0 = 0; k0 < K; k0 += 16) {
        // ---- load A tile: 128 rows x 16 k ----
        #pragma unroll
        for (int it = 0; it < 2; it++) {
            int m = (tid >> 2) + it * 64;
            int gr = bm + m;
            int kk = (tid & 3) << 2;
            float4 v = make_float4(0.f, 0.f, 0.f, 0.f);
            if (gr < M)
                v = *(const float4*)(A + (size_t)gr * lda + k0 + kk);
            float vv[4] = {v.x, v.y, v.z, v.w};
            #pragma unroll
            for (int c = 0; c < 4; c++) {
                uint32_t hi = f2tf32(vv[c]);
                As[0][kk + c][m] = hi;
                if (PASSES == 3)
                    As[1][kk + c][m] = f2tf32(vv[c] - __uint_as_float(hi));
            }
        }
        // ---- load B tile: 16 k x 128 cols ----
        #pragma unroll
        for (int it = 0; it < 2; it++) {
            int k = (tid >> 5) + it * 8;
            int gc = bn + ((tid & 31) << 2);
            const float* bp = Bp + (size_t)(k0 + k) * ldb + gc;
            float vv[4] = {0.f, 0.f, 0.f, 0.f};
            if (gc + 3 < N) {
                float4 v = *(const float4*)bp;
                vv[0] = v.x; vv[1] = v.y; vv[2] = v.z; vv[3] = v.w;
            } else {
                #pragma unroll
                for (int c = 0; c < 4; c++)
                    if (gc + c < N) vv[c] = bp[c];
            }
            int nb = (tid & 31) << 2;
            #pragma unroll
            for (int c = 0; c < 4; c++) {
                uint32_t hi = f2tf32(vv[c]);
                Bs[0][k][nb + c] = hi;
                if (PASSES == 3)
                    Bs[1][k][nb + c] = f2tf32(vv[c] - __uint_as_float(hi));
            }
        }
        __syncthreads();

        // ---- compute: two k8 steps ----
        #pragma unroll
        for (int kb = 0; kb < 16; kb += 8) {
            uint32_t ah[4][4], al[4][4], bh[4][2], bl[4][2];
            int ks = kb + lc;
            #pragma unroll
            for (int i = 0; i < 4; i++) {
                int m = wm * 64 + i * 16 + lr;
                ah[i][0] = As[0][ks][m];     ah[i][1] = As[0][ks][m + 8];
                ah[i][2] = As[0][ks + 4][m]; ah[i][3] = As[0][ks + 4][m + 8];
                if (PASSES == 3) {
                    al[i][0] = As[1][ks][m];     al[i][1] = As[1][ks][m + 8];
                    al[i][2] = As[1][ks + 4][m]; al[i][3] = As[1][ks + 4][m + 8];
                }
            }
            #pragma unroll
            for (int j = 0; j < 4; j++) {
                int n = wn * 32 + j * 8 + lr;
                bh[j][0] = Bs[0][ks][n]; bh[j][1] = Bs[0][ks + 4][n];
                if (PASSES == 3) {
                    bl[j][0] = Bs[1][ks][n]; bl[j][1] = Bs[1][ks + 4][n];
                }
            }
            #pragma unroll
            for (int i = 0; i < 4; i++)
                #pragma unroll
                for (int j = 0; j < 4; j++) {
                    MMA8(acc[i][j], ah[i], bh[j]);
                    if (PASSES == 3) {
                        MMA8(acc[i][j], al[i], bh[j]);
                        MMA8(acc[i][j], ah[i], bl[j]);
                    }
                }
        }
        __syncthreads();
    }

    // ---- epilogue ----
    #pragma unroll
    for (int i = 0; i < 4; i++) {
        int r0 = bm + wm * 64 + i * 16 + lr;
        #pragma unroll
        for (int j = 0; j < 4; j++) {
            int cb = bn + wn * 32 + j * 8 + (lc << 1);
            #pragma unroll
            for (int q = 0; q < 4; q++) {
                int r = r0 + (q >> 1) * 8;
                int c = cb + (q & 1);
                if (r >= M || c >= N) continue;
                float v = acc[i][j][q];
                if (MODE == 1) v += C[(size_t)r * ldc + c];
                else if (MODE == 2) v = softplusf(v + bias[c]);
                C[(size_t)r * ldc + c] = v;
            }
        }
    }
}

// ------------------- causal depthwise conv + silu -------------------------
__global__ void k_conv(const float* __restrict__ cw, const float* __restrict__ cb) {
    int idx = blockIdx.x * 256 + threadIdx.x;
    if (idx >= MROWS * EE) return;
    int row = idx >> 11;
    int e = idx & (EE - 1);
    int b = row >> 10;
    int l = row & 1023;
    float acc = cb[e];
    #pragma unroll
    for (int k = 0; k < 4; k++) {
        int l2 = l - 3 + k;
        if (l2 >= 0)
            acc += g_uz[(size_t)(b * LL + l2) * (2 * EE) + e] * cw[e * 4 + k];
    }
    g_u[idx] = siluf(acc);
}

// ------------------- selective scan, 3-pass chunked -----------------------
__global__ void k_scanA(const float* __restrict__ A_log_l) {
    int c = blockIdx.x, eg = blockIdx.y, b = blockIdx.z;
    int e = eg * 128 + threadIdx.x;
    __shared__ float sBC[CLEN * 32];
    for (int i = threadIdx.x; i < CLEN * 32; i += 128) {
        int tl = i >> 5, j = i & 31;
        sBC[i] = g_dbc[(size_t)(b * LL + c * CLEN + tl) * DBCW + RR + j];
    }
    __syncthreads();
    float Aa[SS], h[SS], P[SS];
    #pragma unroll
    for (int s = 0; s < SS; s++) {
        Aa[s] = -__expf(A_log_l[e * SS + s]);
        h[s] = 0.f; P[s] = 1.f;
    }
    int rowbase = b * LL + c * CLEN;
    for (int tl = 0; tl < CLEN; tl++) {
        size_t off = (size_t)(rowbase + tl) * EE + e;
        float dv = g_delta[off];
        float du = dv * g_u[off];
        #pragma unroll
        for (int s = 0; s < SS; s++) {
            float dA = __expf(dv * Aa[s]);
            h[s] = fmaf(dA, h[s], du * sBC[tl * 32 + s]);
            P[s] *= dA;
        }
    }
    size_t base = ((size_t)c * BB * EE + b * EE + e) * SS;
    float4* Pp = (float4*)(g_P + base);
    float4* Hp = (float4*)(g_hend + base);
    #pragma unroll
    for (int q = 0; q < 4; q++) {
        Pp[q] = make_float4(P[q*4], P[q*4+1], P[q*4+2], P[q*4+3]);
        Hp[q] = make_float4(h[q*4], h[q*4+1], h[q*4+2], h[q*4+3]);
    }
}

__global__ void k_scanB() {
    int idx = blockIdx.x * 256 + threadIdx.x;
    if (idx >= BB * EE) return;
    float h[SS];
    #pragma unroll
    for (int s = 0; s < SS; s++) h[s] = 0.f;
    for (int c = 0; c < NCHUNK; c++) {
        size_t base = ((size_t)c * BB * EE + idx) * SS;
        float4* H0 = (float4*)(g_h0c + base);
        const float4* Pp = (const float4*)(g_P + base);
        const float4* He = (const float4*)(g_hend + base);
        #pragma unroll
        for (int q = 0; q < 4; q++) {
            H0[q] = make_float4(h[q*4], h[q*4+1], h[q*4+2], h[q*4+3]);
            float4 p = Pp[q], he = He[q];
            h[q*4+0] = fmaf(p.x, h[q*4+0], he.x);
            h[q*4+1] = fmaf(p.y, h[q*4+1], he.y);
            h[q*4+2] = fmaf(p.z, h[q*4+2], he.z);
            h[q*4+3] = fmaf(p.w, h[q*4+3], he.w);
        }
    }
}

__global__ void k_scanC(const float* __restrict__ A_log_l, const float* __restrict__ Dsk) {
    int c = blockIdx.x, eg = blockIdx.y, b = blockIdx.z;
    int e = eg * 128 + threadIdx.x;
    __shared__ float sBC[CLEN * 32];
    for (int i = threadIdx.x; i < CLEN * 32; i += 128) {
        int tl = i >> 5, j = i & 31;
        sBC[i] = g_dbc[(size_t)(b * LL + c * CLEN + tl) * DBCW + RR + j];
    }
    __syncthreads();
    float Aa[SS], h[SS];
    #pragma unroll
    for (int s = 0; s < SS; s++) Aa[s] = -__expf(A_log_l[e * SS + s]);
    size_t base = ((size_t)c * BB * EE + b * EE + e) * SS;
    #pragma unroll
    for (int q = 0; q < 4; q++) {
        float4 v = ((const float4*)(g_h0c + base))[q];
        h[q*4+0] = v.x; h[q*4+1] = v.y; h[q*4+2] = v.z; h[q*4+3] = v.w;
    }
    float dsk = Dsk[e];
    int rowbase = b * LL + c * CLEN;
    for (int tl = 0; tl < CLEN; tl++) {
        size_t off = (size_t)(rowbase + tl) * EE + e;
        float dv = g_delta[off];
        float uv = g_u[off];
        float du = dv * uv;
        float y = 0.f;
        #pragma unroll
        for (int s = 0; s < SS; s++) {
            float dA = __expf(dv * Aa[s]);
            h[s] = fmaf(dA, h[s], du * sBC[tl * 32 + s]);
            y = fmaf(h[s], sBC[tl * 32 + 16 + s], y);
        }
        g_y[off] = y + uv * dsk;
    }
}

// ------------------- gate: y * silu(z) ------------------------------------
__global__ void k_gate() {
    int idx = blockIdx.x * 256 + threadIdx.x;
    if (idx >= MROWS * EE) return;
    int row = idx >> 11;
    int e = idx & (EE - 1);
    float z = g_uz[(size_t)row * (2 * EE) + EE + e];
    g_gate[idx] = g_y[idx] * siluf(z);
}

// ------------------- rw scaling -------------------------------------------
__global__ void k_wbar(const float* __restrict__ W_rw_l) {
    int d = blockIdx.x * 256 + threadIdx.x;
    if (d >= DD) return;
    float s = 0.f;
    #pragma unroll
    for (int j = 0; j < SS; j++) s += W_rw_l[d * SS + j];
    g_wbar[d] = s * (1.f / SS);
}

__global__ void k_rw(const float* __restrict__ b_rw_l) {
    int row = blockIdx.x;
    float* hr = g_h + (size_t)row * DD;
    float dot = 0.f;
    for (int d = threadIdx.x; d < DD; d += 256) dot += hr[d] * g_wbar[d];
    __shared__ float red[256];
    red[threadIdx.x] = dot; __syncthreads();
    for (int st = 128; st > 0; st >>= 1) {
        if (threadIdx.x < st) red[threadIdx.x] += red[threadIdx.x + st];
        __syncthreads();
    }
    float bb = 0.f;
    #pragma unroll
    for (int s = 0; s < SS; s++) bb += b_rw_l[s];
    float scale = red[0] + bb * (1.f / SS);
    for (int d = threadIdx.x; d < DD; d += 256) hr[d] *= scale;
}

// ------------------- final layernorm --------------------------------------
__global__ void k_layernorm(const float* __restrict__ gam, const float* __restrict__ bet) {
    int row = blockIdx.x;
    const float* hr = g_h + (size_t)row * DD;
    __shared__ float red[256];
    float s = 0.f;
    for (int d = threadIdx.x; d < DD; d += 256) s += hr[d];
    red[threadIdx.x] = s; __syncthreads();
    for (int st = 128; st > 0; st >>= 1) {
        if (threadIdx.x < st) red[threadIdx.x] += red[threadIdx.x + st];
        __syncthreads();
    }
    float mu = red[0] / DD;
    __syncthreads();
    float v = 0.f;
    for (int d = threadIdx.x; d < DD; d += 256) { float t = hr[d] - mu; v += t * t; }
    red[threadIdx.x] = v; __syncthreads();
    for (int st = 128; st > 0; st >>= 1) {
        if (threadIdx.x < st) red[threadIdx.x] += red[threadIdx.x + st];
        __syncthreads();
    }
    float inv = rsqrtf(red[0] / DD + 1e-5f);
    for (int d = threadIdx.x; d < DD; d += 256)
        g_xn[(size_t)row * DD + d] = (hr[d] - mu) * inv * gam[d] + bet[d];
}

// ------------------- launch -----------------------------------------------
extern "C" void kernel_launch(void* const* d_in, const int* in_sizes, int n_in,
                              void* d_out, int out_size) {
    const int*   x      = (const int*)d_in[0];
    const float* mask   = (const float*)d_in[1];
    const float* emb    = (const float*)d_in[2];
    const float* norm_w = (const float*)d_in[3];
    const float* W_in   = (const float*)d_in[4];
    const float* conv_w = (const float*)d_in[5];
    const float* conv_b = (const float*)d_in[6];
    const float* W_x    = (const float*)d_in[7];
    const float* W_dt   = (const float*)d_in[8];
    const float* b_dt   = (const float*)d_in[9];
    const float* A_log  = (const float*)d_in[10];
    const float* D_skip = (const float*)d_in[11];
    const float* W_out  = (const float*)d_in[12];
    const float* W_rw   = (const float*)d_in[13];
    const float* b_rw   = (const float*)d_in[14];
    const float* ln_g   = (const float*)d_in[15];
    const float* ln_b   = (const float*)d_in[16];
    const float* head_W = (const float*)d_in[17];
    float* out = (float*)d_out;

    float *ph, *pxn, *puz, *pu, *pdbc, *pdelta, *pgate;
    cudaGetSymbolAddress((void**)&ph,     g_h);
    cudaGetSymbolAddress((void**)&pxn,    g_xn);
    cudaGetSymbolAddress((void**)&puz,    g_uz);
    cudaGetSymbolAddress((void**)&pu,     g_u);
    cudaGetSymbolAddress((void**)&pdbc,   g_dbc);
    cudaGetSymbolAddress((void**)&pdelta, g_delta);
    cudaGetSymbolAddress((void**)&pgate,  g_gate);

    k_embed<<<(MROWS * DD + 255) / 256, 256>>>(x, mask, emb);

    for (int l = 0; l < NLAYER; l++) {
        k_rmsnorm<<<MROWS, 256>>>(norm_w + l * DD);

        // uz = xn @ W_in   (2048x1024 @ 1024x4096), 3xTF32
        tgemm<3, 0><<<dim3(2 * EE / 128, MROWS / 128), 256>>>(
            pxn, DD, W_in + (size_t)l * DD * 2 * EE, 2 * EE,
            puz, 2 * EE, MROWS, 2 * EE, DD, nullptr);

        k_conv<<<(MROWS * EE + 255) / 256, 256>>>(conv_w + l * EE * 4, conv_b + l * EE);

        // dbc = u @ W_x   (2048x2048 @ 2048x96), 3xTF32
        tgemm<3, 0><<<dim3(1, MROWS / 128), 256>>>(
            pu, EE, W_x + (size_t)l * EE * DBCW, DBCW,
            pdbc, DBCW, MROWS, DBCW, EE, nullptr);

        // delta = softplus(dr @ W_dt + b_dt)  (2048x64 @ 64x2048), 3xTF32
        tgemm<3, 2><<<dim3(EE / 128, MROWS / 128), 256>>>(
            pdbc, DBCW, W_dt + (size_t)l * RR * EE, EE,
            pdelta, EE, MROWS, EE, RR, b_dt + l * EE);

        k_scanA<<<dim3(NCHUNK, EE / 128, BB), 128>>>(A_log + (size_t)l * EE * SS);
        k_scanB<<<(BB * EE + 255) / 256, 256>>>();
        k_scanC<<<dim3(NCHUNK, EE / 128, BB), 128>>>(A_log + (size_t)l * EE * SS,
                                                     D_skip + l * EE);

        k_gate<<<(MROWS * EE + 255) / 256, 256>>>();

        // h += gate @ W_out  (2048x2048 @ 2048x1024), 3xTF32
        tgemm<3, 1><<<dim3(DD / 128, MROWS / 128), 256>>>(
            pgate, EE, W_out + (size_t)l * EE * DD, DD,
            ph, DD, MROWS, DD, EE, nullptr);

        k_wbar<<<(DD + 255) / 256, 256>>>(W_rw + (size_t)l * DD * SS);
        k_rw<<<MROWS, 256>>>(b_rw + l * SS);
    }

    k_layernorm<<<MROWS, 256>>>(ln_g, ln_b);

    // logits = xn @ head_W  (2048x1024 @ 1024x32000), 1xTF32 (output-only)
    tgemm<1, 0><<<dim3(VV / 128, MROWS / 128), 256>>>(
        pxn, DD, head_W, VV, out, VV, MROWS, VV, DD, nullptr);
}

// round 6
// speedup vs baseline: 3.3301x; 2.5264x over previous
#include <cuda_runtime.h>
#include <cuda_bf16.h>
#include <math.h>
#include <stdint.h>

#define BB 2
#define LL 1024
#define DD 1024
#define EE 2048
#define SS 16
#define RR 64
#define NLAYER 4
#define VV 32000
#define MROWS (BB*LL)
#define NCHUNK 16
#define CLEN (LL/NCHUNK)
#define DBCW 96

// ------------------- scratch (static device globals, no allocs) -------------
__device__ float g_h[MROWS*DD];
__device__ float g_xn[MROWS*DD];
__device__ float g_uz[MROWS*2*EE];
__device__ float g_u[MROWS*EE];
__device__ float g_dbc[MROWS*DBCW];
__device__ float g_delta[MROWS*EE];
__device__ float g_y[MROWS*EE];
__device__ float g_gate[MROWS*EE];
__device__ float g_P[NCHUNK*BB*EE*SS];
__device__ float g_hend[NCHUNK*BB*EE*SS];
__device__ float g_h0c[NCHUNK*BB*EE*SS];
__device__ float g_wbar[DD];

// bf16 hi/lo split operand buffers (16-byte aligned)
__device__ __align__(16) __nv_bfloat16 g_ah[MROWS*EE];
__device__ __align__(16) __nv_bfloat16 g_al[MROWS*EE];
__device__ __align__(16) __nv_bfloat16 g_bh[(size_t)VV*DD];
__device__ __align__(16) __nv_bfloat16 g_bl[(size_t)VV*DD];

__device__ __forceinline__ float siluf(float x) { return x / (1.f + __expf(-x)); }
__device__ __forceinline__ float softplusf(float x) {
    return (x > 20.f) ? x : log1pf(__expf(x));
}

// ------------------- operand conversion -----------------------------------
// activations: fp32 [M,K] (row stride lda) -> packed bf16 hi/lo [M,K]
__global__ void k_cvt_act(const float* __restrict__ A, int M, int K, int lda,
                          __nv_bfloat16* __restrict__ h, __nv_bfloat16* __restrict__ l) {
    int idx = blockIdx.x * 256 + threadIdx.x;
    if (idx >= M * K) return;
    int r = idx / K, c = idx - r * K;
    float x = A[(size_t)r * lda + c];
    __nv_bfloat16 hh = __float2bfloat16(x);
    h[idx] = hh;
    l[idx] = __float2bfloat16(x - __bfloat162float(hh));
}

// weights: fp32 [K,N] row-major -> transposed bf16 hi/lo [N,K]
__global__ void k_cvt_wT(const float* __restrict__ W, int K, int N,
                         __nv_bfloat16* __restrict__ th, __nv_bfloat16* __restrict__ tl) {
    __shared__ float t[32][33];
    int n0 = blockIdx.x * 32, k0 = blockIdx.y * 32;
    int tx = threadIdx.x, ty = threadIdx.y;
    #pragma unroll
    for (int j = 0; j < 32; j += 8) {
        int k = k0 + ty + j, n = n0 + tx;
        t[ty + j][tx] = (k < K && n < N) ? W[(size_t)k * N + n] : 0.f;
    }
    __syncthreads();
    #pragma unroll
    for (int j = 0; j < 32; j += 8) {
        int n = n0 + ty + j, k = k0 + tx;
        if (n < N && k < K) {
            float x = t[tx][ty + j];
            __nv_bfloat16 hh = __float2bfloat16(x);
            th[(size_t)n * K + k] = hh;
            tl[(size_t)n * K + k] = __float2bfloat16(x - __bfloat162float(hh));
        }
    }
}

// ------------------- bf16-split HMMA GEMM ---------------------------------
// C(M,N) = A(M,K) @ B(K,N); A hi/lo [M,K], B hi/lo TRANSPOSED [N,K].
// MODE: 0 = store; 1 = C += AB; 2 = C = softplus(AB + bias[col])
// Tile 128(M) x 128(N) x 32(K); cp.async double-buffer; ldmatrix fragments.
// 3 passes: hh + hl + lh.

__device__ __forceinline__ uint32_t smem_u32(const void* p) {
    uint32_t a;
    asm("{ .reg .u64 t; cvta.to.shared.u64 t, %1; cvt.u32.u64 %0, t; }" : "=r"(a) : "l"(p));
    return a;
}
__device__ __forceinline__ void cpa16(uint32_t s, const void* g, bool v) {
    asm volatile("cp.async.cg.shared.global [%0], [%1], 16, %2;"
                 :: "r"(s), "l"(g), "r"(v ? 16 : 0));
}
// swizzled byte offset within one [128][32] bf16 tile (64B rows)
__device__ __forceinline__ uint32_t swz(int row, int kb) {
    return (uint32_t)(row * 64 + ((((kb >> 4) ^ ((row >> 1) & 3))) << 4) + (kb & 15));
}
#define LDMX4(r, ad) \
    asm volatile("ldmatrix.sync.aligned.m8n8.x4.shared.b16 {%0,%1,%2,%3}, [%4];" \
                 : "=r"((r)[0]), "=r"((r)[1]), "=r"((r)[2]), "=r"((r)[3]) : "r"(ad))
#define MMA16(d, a, b) \
    asm volatile("mma.sync.aligned.m16n8k16.row.col.f32.bf16.bf16.f32 " \
                 "{%0,%1,%2,%3},{%4,%5,%6,%7},{%8,%9},{%0,%1,%2,%3};" \
                 : "+f"((d)[0]), "+f"((d)[1]), "+f"((d)[2]), "+f"((d)[3]) \
                 : "r"((a)[0]), "r"((a)[1]), "r"((a)[2]), "r"((a)[3]), \
                   "r"((b)[0]), "r"((b)[1]))

#define TG_SMEM (2 * 32768)
#define T_AH 0
#define T_AL 8192
#define T_BH 16384
#define T_BL 24576

template<int MODE>
__global__ __launch_bounds__(256, 1)
void tc_gemm(const __nv_bfloat16* __restrict__ Ah, const __nv_bfloat16* __restrict__ Al,
             const __nv_bfloat16* __restrict__ Bh, const __nv_bfloat16* __restrict__ Bl,
             float* __restrict__ C, int ldc, int M, int N, int K,
             const float* __restrict__ bias)
{
    extern __shared__ char smem[];
    uint32_t sb = smem_u32(smem);
    int tid = threadIdx.x, lane = tid & 31, warp = tid >> 5;
    int wm = warp & 1, wn = warp >> 1;
    int bm = blockIdx.y * 128, bn = blockIdx.x * 128;
    int nkt = K >> 5;

    float acc[4][4][4];
    #pragma unroll
    for (int i = 0; i < 4; i++)
        #pragma unroll
        for (int j = 0; j < 4; j++)
            #pragma unroll
            for (int q = 0; q < 4; q++) acc[i][j][q] = 0.f;

    // ---- stage loader: 128 rows x 32 bf16 per tile, 4 tiles ----
    auto load_stage = [&](int kt, int stg) {
        int k0 = kt << 5;
        uint32_t sbase = sb + stg * 32768;
        #pragma unroll
        for (int i = 0; i < 2; i++) {
            int q = tid + i * 256;
            int row = q >> 2, ch = q & 3;
            uint32_t so = (uint32_t)(row * 64 + ((ch ^ ((row >> 1) & 3)) << 4));
            size_t ga = (size_t)(bm + row) * K + k0 + ch * 8;
            cpa16(sbase + T_AH + so, Ah + ga, true);
            cpa16(sbase + T_AL + so, Al + ga, true);
            bool bv = (bn + row) < N;
            size_t gb = bv ? ((size_t)(bn + row) * K + k0 + ch * 8) : 0;
            cpa16(sbase + T_BH + so, Bh + gb, bv);
            cpa16(sbase + T_BL + so, Bl + gb, bv);
        }
        asm volatile("cp.async.commit_group;");
    };

    load_stage(0, 0);

    for (int kt = 0; kt < nkt; kt++) {
        if (kt + 1 < nkt) {
            load_stage(kt + 1, (kt + 1) & 1);
            asm volatile("cp.async.wait_group 1;");
        } else {
            asm volatile("cp.async.wait_group 0;");
        }
        __syncthreads();

        uint32_t base = sb + (kt & 1) * 32768;
        #pragma unroll
        for (int ks = 0; ks < 2; ks++) {
            uint32_t ah[4][4], al[4][4], bh[2][4], bl[2][4];
            #pragma unroll
            for (int i = 0; i < 4; i++) {
                int row = wm * 64 + i * 16 + (lane & 15);
                int kb = ks * 32 + ((lane >> 4) << 4);
                uint32_t off = swz(row, kb);
                LDMX4(ah[i], base + T_AH + off);
                LDMX4(al[i], base + T_AL + off);
            }
            #pragma unroll
            for (int jj = 0; jj < 2; jj++) {
                int g = lane >> 3, rr = lane & 7;
                int n = wn * 32 + jj * 16 + ((g >> 1) << 3) + rr;
                int kb = ks * 32 + ((g & 1) << 4);
                uint32_t off = swz(n, kb);
                LDMX4(bh[jj], base + T_BH + off);
                LDMX4(bl[jj], base + T_BL + off);
            }
            #pragma unroll
            for (int i = 0; i < 4; i++)
                #pragma unroll
                for (int j = 0; j < 4; j++) {
                    uint32_t* bhp = &bh[j >> 1][(j & 1) * 2];
                    uint32_t* blp = &bl[j >> 1][(j & 1) * 2];
                    MMA16(acc[i][j], ah[i], bhp);
                    MMA16(acc[i][j], ah[i], blp);
                    MMA16(acc[i][j], al[i], bhp);
                }
        }
        __syncthreads();
    }

    // ---- epilogue ----
    #pragma unroll
    for (int i = 0; i < 4; i++) {
        int r0 = bm + wm * 64 + i * 16 + (lane >> 2);
        #pragma unroll
        for (int j = 0; j < 4; j++) {
            int c = bn + wn * 32 + j * 8 + (lane & 3) * 2;
            if (c >= N) continue;
            #pragma unroll
            for (int half = 0; half < 2; half++) {
                int r = r0 + half * 8;
                float v0 = acc[i][j][half * 2], v1 = acc[i][j][half * 2 + 1];
                float* cp = C + (size_t)r * ldc + c;
                if (MODE == 1) {
                    float2 old = *(float2*)cp;
                    v0 += old.x; v1 += old.y;
                } else if (MODE == 2) {
                    v0 = softplusf(v0 + bias[c]);
                    v1 = softplusf(v1 + bias[c + 1]);
                }
                *(float2*)cp = make_float2(v0, v1);
            }
        }
    }
}

// ------------------- embed ------------------------------------------------
__global__ void k_embed(const int* __restrict__ x, const float* __restrict__ mask,
                        const float* __restrict__ emb) {
    int idx = blockIdx.x * 256 + threadIdx.x;
    if (idx >= MROWS * DD) return;
    int row = idx >> 10;
    int d = idx & 1023;
    g_h[idx] = emb[(size_t)x[row] * DD + d] * mask[row];
}

// ------------------- rmsnorm ----------------------------------------------
__global__ void k_rmsnorm(const float* __restrict__ w) {
    int row = blockIdx.x;
    const float* hr = g_h + (size_t)row * DD;
    float ss = 0.f;
    for (int d = threadIdx.x; d < DD; d += 256) { float v = hr[d]; ss += v * v; }
    __shared__ float red[256];
    red[threadIdx.x] = ss; __syncthreads();
    for (int st = 128; st > 0; st >>= 1) {
        if (threadIdx.x < st) red[threadIdx.x] += red[threadIdx.x + st];
        __syncthreads();
    }
    float scale = rsqrtf(red[0] / DD + 1e-5f);
    for (int d = threadIdx.x; d < DD; d += 256)
        g_xn[(size_t)row * DD + d] = hr[d] * scale * w[d];
}

// ------------------- causal depthwise conv + silu -------------------------
__global__ void k_conv(const float* __restrict__ cw, const float* __restrict__ cb) {
    int idx = blockIdx.x * 256 + threadIdx.x;
    if (idx >= MROWS * EE) return;
    int row = idx >> 11;
    int e = idx & (EE - 1);
    int b = row >> 10;
    int l = row & 1023;
    float acc = cb[e];
    #pragma unroll
    for (int k = 0; k < 4; k++) {
        int l2 = l - 3 + k;
        if (l2 >= 0)
            acc += g_uz[(size_t)(b * LL + l2) * (2 * EE) + e] * cw[e * 4 + k];
    }
    g_u[idx] = siluf(acc);
}

// ------------------- selective scan, 3-pass chunked -----------------------
__global__ void k_scanA(const float* __restrict__ A_log_l) {
    int c = blockIdx.x, eg = blockIdx.y, b = blockIdx.z;
    int e = eg * 128 + threadIdx.x;
    __shared__ float sBC[CLEN * 32];
    for (int i = threadIdx.x; i < CLEN * 32; i += 128) {
        int tl = i >> 5, j = i & 31;
        sBC[i] = g_dbc[(size_t)(b * LL + c * CLEN + tl) * DBCW + RR + j];
    }
    __syncthreads();
    float Aa[SS], h[SS], P[SS];
    #pragma unroll
    for (int s = 0; s < SS; s++) {
        Aa[s] = -__expf(A_log_l[e * SS + s]);
        h[s] = 0.f; P[s] = 1.f;
    }
    int rowbase = b * LL + c * CLEN;
    for (int tl = 0; tl < CLEN; tl++) {
        size_t off = (size_t)(rowbase + tl) * EE + e;
        float dv = g_delta[off];
        float du = dv * g_u[off];
        #pragma unroll
        for (int s = 0; s < SS; s++) {
            float dA = __expf(dv * Aa[s]);
            h[s] = fmaf(dA, h[s], du * sBC[tl * 32 + s]);
            P[s] *= dA;
        }
    }
    size_t base = ((size_t)c * BB * EE + b * EE + e) * SS;
    float4* Pp = (float4*)(g_P + base);
    float4* Hp = (float4*)(g_hend + base);
    #pragma unroll
    for (int q = 0; q < 4; q++) {
        Pp[q] = make_float4(P[q*4], P[q*4+1], P[q*4+2], P[q*4+3]);
        Hp[q] = make_float4(h[q*4], h[q*4+1], h[q*4+2], h[q*4+3]);
    }
}

__global__ void k_scanB() {
    int idx = blockIdx.x * 256 + threadIdx.x;
    if (idx >= BB * EE) return;
    float h[SS];
    #pragma unroll
    for (int s = 0; s < SS; s++) h[s] = 0.f;
    for (int c = 0; c < NCHUNK; c++) {
        size_t base = ((size_t)c * BB * EE + idx) * SS;
        float4* H0 = (float4*)(g_h0c + base);
        const float4* Pp = (const float4*)(g_P + base);
        const float4* He = (const float4*)(g_hend + base);
        #pragma unroll
        for (int q = 0; q < 4; q++) {
            H0[q] = make_float4(h[q*4], h[q*4+1], h[q*4+2], h[q*4+3]);
            float4 p = Pp[q], he = He[q];
            h[q*4+0] = fmaf(p.x, h[q*4+0], he.x);
            h[q*4+1] = fmaf(p.y, h[q*4+1], he.y);
            h[q*4+2] = fmaf(p.z, h[q*4+2], he.z);
            h[q*4+3] = fmaf(p.w, h[q*4+3], he.w);
        }
    }
}

__global__ void k_scanC(const float* __restrict__ A_log_l, const float* __restrict__ Dsk) {
    int c = blockIdx.x, eg = blockIdx.y, b = blockIdx.z;
    int e = eg * 128 + threadIdx.x;
    __shared__ float sBC[CLEN * 32];
    for (int i = threadIdx.x; i < CLEN * 32; i += 128) {
        int tl = i >> 5, j = i & 31;
        sBC[i] = g_dbc[(size_t)(b * LL + c * CLEN + tl) * DBCW + RR + j];
    }
    __syncthreads();
    float Aa[SS], h[SS];
    #pragma unroll
    for (int s = 0; s < SS; s++) Aa[s] = -__expf(A_log_l[e * SS + s]);
    size_t base = ((size_t)c * BB * EE + b * EE + e) * SS;
    #pragma unroll
    for (int q = 0; q < 4; q++) {
        float4 v = ((const float4*)(g_h0c + base))[q];
        h[q*4+0] = v.x; h[q*4+1] = v.y; h[q*4+2] = v.z; h[q*4+3] = v.w;
    }
    float dsk = Dsk[e];
    int rowbase = b * LL + c * CLEN;
    for (int tl = 0; tl < CLEN; tl++) {
        size_t off = (size_t)(rowbase + tl) * EE + e;
        float dv = g_delta[off];
        float uv = g_u[off];
        float du = dv * uv;
        float y = 0.f;
        #pragma unroll
        for (int s = 0; s < SS; s++) {
            float dA = __expf(dv * Aa[s]);
            h[s] = fmaf(dA, h[s], du * sBC[tl * 32 + s]);
            y = fmaf(h[s], sBC[tl * 32 + 16 + s], y);
        }
        g_y[off] = y + uv * dsk;
    }
}

// ------------------- gate: y * silu(z) ------------------------------------
__global__ void k_gate() {
    int idx = blockIdx.x * 256 + threadIdx.x;
    if (idx >= MROWS * EE) return;
    int row = idx >> 11;
    int e = idx & (EE - 1);
    float z = g_uz[(size_t)row * (2 * EE) + EE + e];
    g_gate[idx] = g_y[idx] * siluf(z);
}

// ------------------- rw scaling -------------------------------------------
__global__ void k_wbar(const float* __restrict__ W_rw_l) {
    int d = blockIdx.x * 256 + threadIdx.x;
    if (d >= DD) return;
    float s = 0.f;
    #pragma unroll
    for (int j = 0; j < SS; j++) s += W_rw_l[d * SS + j];
    g_wbar[d] = s * (1.f / SS);
}

__global__ void k_rw(const float* __restrict__ b_rw_l) {
    int row = blockIdx.x;
    float* hr = g_h + (size_t)row * DD;
    float dot = 0.f;
    for (int d = threadIdx.x; d < DD; d += 256) dot += hr[d] * g_wbar[d];
    __shared__ float red[256];
    red[threadIdx.x] = dot; __syncthreads();
    for (int st = 128; st > 0; st >>= 1) {
        if (threadIdx.x < st) red[threadIdx.x] += red[threadIdx.x + st];
        __syncthreads();
    }
    float bb = 0.f;
    #pragma unroll
    for (int s = 0; s < SS; s++) bb += b_rw_l[s];
    float scale = red[0] + bb * (1.f / SS);
    for (int d = threadIdx.x; d < DD; d += 256) hr[d] *= scale;
}

// ------------------- final layernorm --------------------------------------
__global__ void k_layernorm(const float* __restrict__ gam, const float* __restrict__ bet) {
    int row = blockIdx.x;
    const float* hr = g_h + (size_t)row * DD;
    __shared__ float red[256];
    float s = 0.f;
    for (int d = threadIdx.x; d < DD; d += 256) s += hr[d];
    red[threadIdx.x] = s; __syncthreads();
    for (int st = 128; st > 0; st >>= 1) {
        if (threadIdx.x < st) red[threadIdx.x] += red[threadIdx.x + st];
        __syncthreads();
    }
    float mu = red[0] / DD;
    __syncthreads();
    float v = 0.f;
    for (int d = threadIdx.x; d < DD; d += 256) { float t = hr[d] - mu; v += t * t; }
    red[threadIdx.x] = v; __syncthreads();
    for (int st = 128; st > 0; st >>= 1) {
        if (threadIdx.x < st) red[threadIdx.x] += red[threadIdx.x + st];
        __syncthreads();
    }
    float inv = rsqrtf(red[0] / DD + 1e-5f);
    for (int d = threadIdx.x; d < DD; d += 256)
        g_xn[(size_t)row * DD + d] = (hr[d] - mu) * inv * gam[d] + bet[d];
}

// ------------------- launch -----------------------------------------------
extern "C" void kernel_launch(void* const* d_in, const int* in_sizes, int n_in,
                              void* d_out, int out_size) {
    const int*   x      = (const int*)d_in[0];
    const float* mask   = (const float*)d_in[1];
    const float* emb    = (const float*)d_in[2];
    const float* norm_w = (const float*)d_in[3];
    const float* W_in   = (const float*)d_in[4];
    const float* conv_w = (const float*)d_in[5];
    const float* conv_b = (const float*)d_in[6];
    const float* W_x    = (const float*)d_in[7];
    const float* W_dt   = (const float*)d_in[8];
    const float* b_dt   = (const float*)d_in[9];
    const float* A_log  = (const float*)d_in[10];
    const float* D_skip = (const float*)d_in[11];
    const float* W_out  = (const float*)d_in[12];
    const float* W_rw   = (const float*)d_in[13];
    const float* b_rw   = (const float*)d_in[14];
    const float* ln_g   = (const float*)d_in[15];
    const float* ln_b   = (const float*)d_in[16];
    const float* head_W = (const float*)d_in[17];
    float* out = (float*)d_out;

    float *ph, *pxn, *puz, *pu, *pdbc, *pdelta, *pgate;
    __nv_bfloat16 *pah, *pal, *pbh, *pbl;
    cudaGetSymbolAddress((void**)&ph,     g_h);
    cudaGetSymbolAddress((void**)&pxn,    g_xn);
    cudaGetSymbolAddress((void**)&puz,    g_uz);
    cudaGetSymbolAddress((void**)&pu,     g_u);
    cudaGetSymbolAddress((void**)&pdbc,   g_dbc);
    cudaGetSymbolAddress((void**)&pdelta, g_delta);
    cudaGetSymbolAddress((void**)&pgate,  g_gate);
    cudaGetSymbolAddress((void**)&pah,    g_ah);
    cudaGetSymbolAddress((void**)&pal,    g_al);
    cudaGetSymbolAddress((void**)&pbh,    g_bh);
    cudaGetSymbolAddress((void**)&pbl,    g_bl);

    cudaFuncSetAttribute(tc_gemm<0>, cudaFuncAttributeMaxDynamicSharedMemorySize, TG_SMEM);
    cudaFuncSetAttribute(tc_gemm<1>, cudaFuncAttributeMaxDynamicSharedMemorySize, TG_SMEM);
    cudaFuncSetAttribute(tc_gemm<2>, cudaFuncAttributeMaxDynamicSharedMemorySize, TG_SMEM);

    dim3 cvtb(32, 8);

    k_embed<<<(MROWS * DD + 255) / 256, 256>>>(x, mask, emb);

    for (int l = 0; l < NLAYER; l++) {
        k_rmsnorm<<<MROWS, 256>>>(norm_w + l * DD);

        // uz = xn @ W_in   (2048x1024 @ 1024x4096)
        k_cvt_act<<<(MROWS * DD + 255) / 256, 256>>>(pxn, MROWS, DD, DD, pah, pal);
        k_cvt_wT<<<dim3((2 * EE + 31) / 32, (DD + 31) / 32), cvtb>>>(
            W_in + (size_t)l * DD * 2 * EE, DD, 2 * EE, pbh, pbl);
        tc_gemm<0><<<dim3(2 * EE / 128, MROWS / 128), 256, TG_SMEM>>>(
            pah, pal, pbh, pbl, puz, 2 * EE, MROWS, 2 * EE, DD, nullptr);

        k_conv<<<(MROWS * EE + 255) / 256, 256>>>(conv_w + l * EE * 4, conv_b + l * EE);

        // dbc = u @ W_x   (2048x2048 @ 2048x96)
        k_cvt_act<<<(MROWS * EE + 255) / 256, 256>>>(pu, MROWS, EE, EE, pah, pal);
        k_cvt_wT<<<dim3((DBCW + 31) / 32, (EE + 31) / 32), cvtb>>>(
            W_x + (size_t)l * EE * DBCW, EE, DBCW, pbh, pbl);
        tc_gemm<0><<<dim3(1, MROWS / 128), 256, TG_SMEM>>>(
            pah, pal, pbh, pbl, pdbc, DBCW, MROWS, DBCW, EE, nullptr);

        // delta = softplus(dr @ W_dt + b_dt)  (2048x64 @ 64x2048)
        k_cvt_act<<<(MROWS * RR + 255) / 256, 256>>>(pdbc, MROWS, RR, DBCW, pah, pal);
        k_cvt_wT<<<dim3((EE + 31) / 32, (RR + 31) / 32), cvtb>>>(
            W_dt + (size_t)l * RR * EE, RR, EE, pbh, pbl);
        tc_gemm<2><<<dim3(EE / 128, MROWS / 128), 256, TG_SMEM>>>(
            pah, pal, pbh, pbl, pdelta, EE, MROWS, EE, RR, b_dt + l * EE);

        k_scanA<<<dim3(NCHUNK, EE / 128, BB), 128>>>(A_log + (size_t)l * EE * SS);
        k_scanB<<<(BB * EE + 255) / 256, 256>>>();
        k_scanC<<<dim3(NCHUNK, EE / 128, BB), 128>>>(A_log + (size_t)l * EE * SS,
                                                     D_skip + l * EE);

        k_gate<<<(MROWS * EE + 255) / 256, 256>>>();

        // h += gate @ W_out  (2048x2048 @ 2048x1024)
        k_cvt_act<<<(MROWS * EE + 255) / 256, 256>>>(pgate, MROWS, EE, EE, pah, pal);
        k_cvt_wT<<<dim3((DD + 31) / 32, (EE + 31) / 32), cvtb>>>(
            W_out + (size_t)l * EE * DD, EE, DD, pbh, pbl);
        tc_gemm<1><<<dim3(DD / 128, MROWS / 128), 256, TG_SMEM>>>(
            pah, pal, pbh, pbl, ph, DD, MROWS, DD, EE, nullptr);

        k_wbar<<<(DD + 255) / 256, 256>>>(W_rw + (size_t)l * DD * SS);
        k_rw<<<MROWS, 256>>>(b_rw + l * SS);
    }

    k_layernorm<<<MROWS, 256>>>(ln_g, ln_b);

    // logits = xn @ head_W  (2048x1024 @ 1024x32000)
    k_cvt_act<<<(MROWS * DD + 255) / 256, 256>>>(pxn, MROWS, DD, DD, pah, pal);
    k_cvt_wT<<<dim3((VV + 31) / 32, (DD + 31) / 32), cvtb>>>(head_W, DD, VV, pbh, pbl);
    tc_gemm<0><<<dim3(VV / 128, MROWS / 128), 256, TG_SMEM>>>(
        pah, pal, pbh, pbl, out, VV, MROWS, VV, DD, nullptr);
}

// round 7
// speedup vs baseline: 3.7088x; 1.1137x over previous
#include <cuda_runtime.h>
#include <cuda_bf16.h>
#include <math.h>
#include <stdint.h>

#define BB 2
#define LL 1024
#define DD 1024
#define EE 2048
#define SS 16
#define RR 64
#define NLAYER 4
#define VV 32000
#define MROWS (BB*LL)
#define NCHUNK 16
#define CLEN (LL/NCHUNK)
#define DBCW 96

// ------------------- scratch (static device globals, no allocs) -------------
__device__ float g_h[MROWS*DD];
__device__ float g_uz[MROWS*2*EE];
__device__ float g_u[MROWS*EE];
__device__ float g_dbc[MROWS*DBCW];
__device__ float g_delta[MROWS*EE];
__device__ float g_P[NCHUNK*BB*EE*SS];
__device__ float g_hend[NCHUNK*BB*EE*SS];
__device__ float g_h0c[NCHUNK*BB*EE*SS];
__device__ float g_wbar[DD+1];

// bf16 hi/lo split operand buffers (16-byte aligned)
__device__ __align__(16) __nv_bfloat16 g_ah[MROWS*EE];
__device__ __align__(16) __nv_bfloat16 g_al[MROWS*EE];
__device__ __align__(16) __nv_bfloat16 g_bh[(size_t)VV*DD];
__device__ __align__(16) __nv_bfloat16 g_bl[(size_t)VV*DD];

__device__ __forceinline__ float siluf(float x) { return x / (1.f + __expf(-x)); }
__device__ __forceinline__ float softplusf(float x) {
    return (x > 20.f) ? x : log1pf(__expf(x));
}
__device__ __forceinline__ void split_store(float x, __nv_bfloat16* h, __nv_bfloat16* l,
                                            size_t idx) {
    __nv_bfloat16 hh = __float2bfloat16(x);
    h[idx] = hh;
    l[idx] = __float2bfloat16(x - __bfloat162float(hh));
}

// ------------------- conversions ------------------------------------------
__global__ void k_cvt_act(const float* __restrict__ A, int M, int K, int lda,
                          __nv_bfloat16* __restrict__ h, __nv_bfloat16* __restrict__ l) {
    int idx = blockIdx.x * 256 + threadIdx.x;
    if (idx >= M * K) return;
    int r = idx / K, c = idx - r * K;
    split_store(A[(size_t)r * lda + c], h, l, idx);
}

// weights: fp32 [K,N] row-major -> transposed bf16 hi/lo [N,K]
__global__ void k_cvt_wT(const float* __restrict__ W, int K, int N,
                         __nv_bfloat16* __restrict__ th, __nv_bfloat16* __restrict__ tl) {
    __shared__ float t[32][33];
    int n0 = blockIdx.x * 32, k0 = blockIdx.y * 32;
    int tx = threadIdx.x, ty = threadIdx.y;
    #pragma unroll
    for (int j = 0; j < 32; j += 8) {
        int k = k0 + ty + j, n = n0 + tx;
        t[ty + j][tx] = (k < K && n < N) ? W[(size_t)k * N + n] : 0.f;
    }
    __syncthreads();
    #pragma unroll
    for (int j = 0; j < 32; j += 8) {
        int n = n0 + ty + j, k = k0 + tx;
        if (n < N && k < K)
            split_store(t[tx][ty + j], th, tl, (size_t)n * K + k);
    }
}

__global__ void k_zero(float* p, int n) {
    int idx = blockIdx.x * 256 + threadIdx.x;
    if (idx < n) p[idx] = 0.f;
}

// ------------------- bf16-split HMMA GEMM ---------------------------------
__device__ __forceinline__ uint32_t smem_u32(const void* p) {
    uint32_t a;
    asm("{ .reg .u64 t; cvta.to.shared.u64 t, %1; cvt.u32.u64 %0, t; }" : "=r"(a) : "l"(p));
    return a;
}
__device__ __forceinline__ void cpa16(uint32_t s, const void* g, bool v) {
    asm volatile("cp.async.cg.shared.global [%0], [%1], 16, %2;"
                 :: "r"(s), "l"(g), "r"(v ? 16 : 0));
}
__device__ __forceinline__ uint32_t swz(int row, int kb) {
    return (uint32_t)(row * 64 + ((((kb >> 4) ^ ((row >> 1) & 3))) << 4) + (kb & 15));
}
#define LDMX4(r, ad) \
    asm volatile("ldmatrix.sync.aligned.m8n8.x4.shared.b16 {%0,%1,%2,%3}, [%4];" \
                 : "=r"((r)[0]), "=r"((r)[1]), "=r"((r)[2]), "=r"((r)[3]) : "r"(ad))
#define MMA16(d, a, b) \
    asm volatile("mma.sync.aligned.m16n8k16.row.col.f32.bf16.bf16.f32 " \
                 "{%0,%1,%2,%3},{%4,%5,%6,%7},{%8,%9},{%0,%1,%2,%3};" \
                 : "+f"((d)[0]), "+f"((d)[1]), "+f"((d)[2]), "+f"((d)[3]) \
                 : "r"((a)[0]), "r"((a)[1]), "r"((a)[2]), "r"((a)[3]), \
                   "r"((b)[0]), "r"((b)[1]))

#define TG_SMEM (3 * 32768)
#define T_AH 0
#define T_AL 8192
#define T_BH 16384
#define T_BL 24576

// MODE: 0 store, 1 C+=AB, 2 softplus(AB+bias), 3 atomicAdd (split-K via blockIdx.z)
template<int MODE>
__global__ __launch_bounds__(256, 1)
void tc_gemm(const __nv_bfloat16* __restrict__ Ah, const __nv_bfloat16* __restrict__ Al,
             const __nv_bfloat16* __restrict__ Bh, const __nv_bfloat16* __restrict__ Bl,
             float* __restrict__ C, int ldc, int M, int N, int K,
             const float* __restrict__ bias)
{
    extern __shared__ char smem[];
    uint32_t sb = smem_u32(smem);
    int tid = threadIdx.x, lane = tid & 31, warp = tid >> 5;
    int wm = warp & 1, wn = warp >> 1;
    int bm = blockIdx.y * 128, bn = blockIdx.x * 128;
    int kn = K / gridDim.z;
    int t0 = (blockIdx.z * kn) >> 5, tn = kn >> 5;

    float acc[4][4][4];
    #pragma unroll
    for (int i = 0; i < 4; i++)
        #pragma unroll
        for (int j = 0; j < 4; j++)
            #pragma unroll
            for (int q = 0; q < 4; q++) acc[i][j][q] = 0.f;

    auto load_stage = [&](int kt, int stg) {
        int k0 = kt << 5;
        uint32_t sbase = sb + stg * 32768;
        #pragma unroll
        for (int i = 0; i < 2; i++) {
            int q = tid + i * 256;
            int row = q >> 2, ch = q & 3;
            uint32_t so = (uint32_t)(row * 64 + ((ch ^ ((row >> 1) & 3)) << 4));
            size_t ga = (size_t)(bm + row) * K + k0 + ch * 8;
            cpa16(sbase + T_AH + so, Ah + ga, true);
            cpa16(sbase + T_AL + so, Al + ga, true);
            bool bv = (bn + row) < N;
            size_t gb = bv ? ((size_t)(bn + row) * K + k0 + ch * 8) : 0;
            cpa16(sbase + T_BH + so, Bh + gb, bv);
            cpa16(sbase + T_BL + so, Bl + gb, bv);
        }
        asm volatile("cp.async.commit_group;");
    };

    load_stage(t0, 0);
    if (tn > 1) load_stage(t0 + 1, 1);
    else asm volatile("cp.async.commit_group;");

    for (int i = 0; i < tn; i++) {
        if (i + 2 < tn) load_stage(t0 + i + 2, (i + 2) % 3);
        else asm volatile("cp.async.commit_group;");
        asm volatile("cp.async.wait_group 2;");
        __syncthreads();

        uint32_t base = sb + (i % 3) * 32768;
        #pragma unroll
        for (int ks = 0; ks < 2; ks++) {
            uint32_t ah[4][4], al[4][4], bh[2][4], bl[2][4];
            #pragma unroll
            for (int ii = 0; ii < 4; ii++) {
                int row = wm * 64 + ii * 16 + (lane & 15);
                int kb = ks * 32 + ((lane >> 4) << 4);
                uint32_t off = swz(row, kb);
                LDMX4(ah[ii], base + T_AH + off);
                LDMX4(al[ii], base + T_AL + off);
            }
            #pragma unroll
            for (int jj = 0; jj < 2; jj++) {
                int g = lane >> 3, rr = lane & 7;
                int n = wn * 32 + jj * 16 + ((g >> 1) << 3) + rr;
                int kb = ks * 32 + ((g & 1) << 4);
                uint32_t off = swz(n, kb);
                LDMX4(bh[jj], base + T_BH + off);
                LDMX4(bl[jj], base + T_BL + off);
            }
            #pragma unroll
            for (int ii = 0; ii < 4; ii++)
                #pragma unroll
                for (int j = 0; j < 4; j++) {
                    uint32_t* bhp = &bh[j >> 1][(j & 1) * 2];
                    uint32_t* blp = &bl[j >> 1][(j & 1) * 2];
                    MMA16(acc[ii][j], ah[ii], bhp);
                    MMA16(acc[ii][j], ah[ii], blp);
                    MMA16(acc[ii][j], al[ii], bhp);
                }
        }
        __syncthreads();
    }

    #pragma unroll
    for (int i = 0; i < 4; i++) {
        int r0 = bm + wm * 64 + i * 16 + (lane >> 2);
        #pragma unroll
        for (int j = 0; j < 4; j++) {
            int c = bn + wn * 32 + j * 8 + (lane & 3) * 2;
            if (c >= N) continue;
            #pragma unroll
            for (int half = 0; half < 2; half++) {
                int r = r0 + half * 8;
                float v0 = acc[i][j][half * 2], v1 = acc[i][j][half * 2 + 1];
                float* cp = C + (size_t)r * ldc + c;
                if (MODE == 3) {
                    atomicAdd(cp, v0); atomicAdd(cp + 1, v1);
                } else {
                    if (MODE == 1) {
                        float2 old = *(float2*)cp;
                        v0 += old.x; v1 += old.y;
                    } else if (MODE == 2) {
                        v0 = softplusf(v0 + bias[c]);
                        v1 = softplusf(v1 + bias[c + 1]);
                    }
                    *(float2*)cp = make_float2(v0, v1);
                }
            }
        }
    }
}

// ------------------- embed ------------------------------------------------
__global__ void k_embed(const int* __restrict__ x, const float* __restrict__ mask,
                        const float* __restrict__ emb) {
    int idx = blockIdx.x * 256 + threadIdx.x;
    if (idx >= MROWS * DD) return;
    int row = idx >> 10;
    int d = idx & 1023;
    g_h[idx] = emb[(size_t)x[row] * DD + d] * mask[row];
}

// ------------------- rmsnorm (layer 0) -> split bf16 ----------------------
__global__ void k_rms_split(const float* __restrict__ w) {
    int row = blockIdx.x;
    const float* hr = g_h + (size_t)row * DD;
    float ss = 0.f;
    for (int d = threadIdx.x; d < DD; d += 256) { float v = hr[d]; ss += v * v; }
    __shared__ float red[256];
    red[threadIdx.x] = ss; __syncthreads();
    for (int st = 128; st > 0; st >>= 1) {
        if (threadIdx.x < st) red[threadIdx.x] += red[threadIdx.x + st];
        __syncthreads();
    }
    float scale = rsqrtf(red[0] / DD + 1e-5f);
    for (int d = threadIdx.x; d < DD; d += 256)
        split_store(hr[d] * scale * w[d], g_ah, g_al, (size_t)row * DD + d);
}

// ------------------- fused rw-scale + rmsnorm -> split --------------------
__global__ void k_rw_rms(const float* __restrict__ w) {
    int row = blockIdx.x;
    float* hr = g_h + (size_t)row * DD;
    float dot = 0.f, ss = 0.f;
    for (int d = threadIdx.x; d < DD; d += 256) {
        float v = hr[d];
        dot += v * g_wbar[d];
        ss += v * v;
    }
    __shared__ float r1[256], r2[256];
    r1[threadIdx.x] = dot; r2[threadIdx.x] = ss; __syncthreads();
    for (int st = 128; st > 0; st >>= 1) {
        if (threadIdx.x < st) {
            r1[threadIdx.x] += r1[threadIdx.x + st];
            r2[threadIdx.x] += r2[threadIdx.x + st];
        }
        __syncthreads();
    }
    float scale = r1[0] + g_wbar[DD];
    float inv = rsqrtf(scale * scale * r2[0] / DD + 1e-5f);
    for (int d = threadIdx.x; d < DD; d += 256) {
        float hv = hr[d] * scale;
        hr[d] = hv;
        split_store(hv * inv * w[d], g_ah, g_al, (size_t)row * DD + d);
    }
}

// ------------------- fused rw-scale + layernorm -> split ------------------
__global__ void k_rw_ln(const float* __restrict__ gam, const float* __restrict__ bet) {
    int row = blockIdx.x;
    const float* hr = g_h + (size_t)row * DD;
    float dot = 0.f, ss = 0.f, sum = 0.f;
    for (int d = threadIdx.x; d < DD; d += 256) {
        float v = hr[d];
        dot += v * g_wbar[d];
        ss += v * v;
        sum += v;
    }
    __shared__ float r1[256], r2[256], r3[256];
    r1[threadIdx.x] = dot; r2[threadIdx.x] = ss; r3[threadIdx.x] = sum; __syncthreads();
    for (int st = 128; st > 0; st >>= 1) {
        if (threadIdx.x < st) {
            r1[threadIdx.x] += r1[threadIdx.x + st];
            r2[threadIdx.x] += r2[threadIdx.x + st];
            r3[threadIdx.x] += r3[threadIdx.x + st];
        }
        __syncthreads();
    }
    float scale = r1[0] + g_wbar[DD];
    float mean = scale * r3[0] / DD;
    float var = scale * scale * r2[0] / DD - mean * mean;
    float inv = rsqrtf(var + 1e-5f);
    for (int d = threadIdx.x; d < DD; d += 256) {
        float hv = hr[d] * scale;
        split_store((hv - mean) * inv * gam[d] + bet[d], g_ah, g_al, (size_t)row * DD + d);
    }
}

// ------------------- causal dwconv + silu -> u fp32 + split ---------------
__global__ void k_conv_split(const float* __restrict__ cw, const float* __restrict__ cb) {
    int idx = blockIdx.x * 256 + threadIdx.x;
    if (idx >= MROWS * EE) return;
    int row = idx >> 11;
    int e = idx & (EE - 1);
    int b = row >> 10;
    int l = row & 1023;
    float acc = cb[e];
    #pragma unroll
    for (int k = 0; k < 4; k++) {
        int l2 = l - 3 + k;
        if (l2 >= 0)
            acc += g_uz[(size_t)(b * LL + l2) * (2 * EE) + e] * cw[e * 4 + k];
    }
    float u = siluf(acc);
    g_u[idx] = u;
    split_store(u, g_ah, g_al, idx);
}

// ------------------- selective scan (integer-power fast path) -------------
__global__ void k_scanA2(const float* __restrict__ A_log_l) {
    int c = blockIdx.x, eg = blockIdx.y, b = blockIdx.z;
    int e = eg * 128 + threadIdx.x;
    __shared__ float sB[CLEN * 16];
    for (int i = threadIdx.x; i < CLEN * 16; i += 128) {
        int tl = i >> 4, j = i & 15;
        sB[i] = g_dbc[(size_t)(b * LL + c * CLEN + tl) * DBCW + RR + j];
    }
    __syncthreads();
    float cs[SS];
    bool consec = true;
    #pragma unroll
    for (int s = 0; s < SS; s++) {
        cs[s] = __expf(A_log_l[e * SS + s]);
        consec = consec && (fabsf(cs[s] - (float)(s + 1)) < 1e-4f);
    }
    float h[SS];
    #pragma unroll
    for (int s = 0; s < SS; s++) h[s] = 0.f;
    float dsum = 0.f;
    int rowbase = b * LL + c * CLEN;
    if (consec) {
        for (int tl = 0; tl < CLEN; tl++) {
            size_t off = (size_t)(rowbase + tl) * EE + e;
            float dv = g_delta[off];
            float du = dv * g_u[off];
            dsum += dv;
            float q = __expf(-dv), p = 1.f;
            #pragma unroll
            for (int s = 0; s < SS; s++) {
                p *= q;
                h[s] = fmaf(p, h[s], du * sB[tl * 16 + s]);
            }
        }
    } else {
        for (int tl = 0; tl < CLEN; tl++) {
            size_t off = (size_t)(rowbase + tl) * EE + e;
            float dv = g_delta[off];
            float du = dv * g_u[off];
            dsum += dv;
            #pragma unroll
            for (int s = 0; s < SS; s++) {
                float dA = __expf(-dv * cs[s]);
                h[s] = fmaf(dA, h[s], du * sB[tl * 16 + s]);
            }
        }
    }
    float P[SS];
    if (consec) {
        float Q = __expf(-dsum), p = 1.f;
        #pragma unroll
        for (int s = 0; s < SS; s++) { p *= Q; P[s] = p; }
    } else {
        #pragma unroll
        for (int s = 0; s < SS; s++) P[s] = __expf(-dsum * cs[s]);
    }
    size_t base = ((size_t)c * BB * EE + b * EE + e) * SS;
    float4* Pp = (float4*)(g_P + base);
    float4* Hp = (float4*)(g_hend + base);
    #pragma unroll
    for (int q = 0; q < 4; q++) {
        Pp[q] = make_float4(P[q*4], P[q*4+1], P[q*4+2], P[q*4+3]);
        Hp[q] = make_float4(h[q*4], h[q*4+1], h[q*4+2], h[q*4+3]);
    }
}

__global__ void k_scanB() {
    int idx = blockIdx.x * 256 + threadIdx.x;
    if (idx >= BB * EE) return;
    float h[SS];
    #pragma unroll
    for (int s = 0; s < SS; s++) h[s] = 0.f;
    for (int c = 0; c < NCHUNK; c++) {
        size_t base = ((size_t)c * BB * EE + idx) * SS;
        float4* H0 = (float4*)(g_h0c + base);
        const float4* Pp = (const float4*)(g_P + base);
        const float4* He = (const float4*)(g_hend + base);
        #pragma unroll
        for (int q = 0; q < 4; q++) {
            H0[q] = make_float4(h[q*4], h[q*4+1], h[q*4+2], h[q*4+3]);
            float4 p = Pp[q], he = He[q];
            h[q*4+0] = fmaf(p.x, h[q*4+0], he.x);
            h[q*4+1] = fmaf(p.y, h[q*4+1], he.y);
            h[q*4+2] = fmaf(p.z, h[q*4+2], he.z);
            h[q*4+3] = fmaf(p.w, h[q*4+3], he.w);
        }
    }
}

// scanC fused with gate: writes gate = (y + u*Dsk) * silu(z) as bf16 split
__global__ void k_scanC2(const float* __restrict__ A_log_l, const float* __restrict__ Dsk) {
    int c = blockIdx.x, eg = blockIdx.y, b = blockIdx.z;
    int e = eg * 128 + threadIdx.x;
    __shared__ float sBC[CLEN * 32];
    for (int i = threadIdx.x; i < CLEN * 32; i += 128) {
        int tl = i >> 5, j = i & 31;
        sBC[i] = g_dbc[(size_t)(b * LL + c * CLEN + tl) * DBCW + RR + j];
    }
    __syncthreads();
    float cs[SS];
    bool consec = true;
    #pragma unroll
    for (int s = 0; s < SS; s++) {
        cs[s] = __expf(A_log_l[e * SS + s]);
        consec = consec && (fabsf(cs[s] - (float)(s + 1)) < 1e-4f);
    }
    float h[SS];
    size_t base = ((size_t)c * BB * EE + b * EE + e) * SS;
    #pragma unroll
    for (int q = 0; q < 4; q++) {
        float4 v = ((const float4*)(g_h0c + base))[q];
        h[q*4+0] = v.x; h[q*4+1] = v.y; h[q*4+2] = v.z; h[q*4+3] = v.w;
    }
    float dsk = Dsk[e];
    int rowbase = b * LL + c * CLEN;
    if (consec) {
        for (int tl = 0; tl < CLEN; tl++) {
            size_t off = (size_t)(rowbase + tl) * EE + e;
            float dv = g_delta[off];
            float uv = g_u[off];
            float du = dv * uv;
            float q = __expf(-dv), p = 1.f, y = 0.f;
            #pragma unroll
            for (int s = 0; s < SS; s++) {
                p *= q;
                h[s] = fmaf(p, h[s], du * sBC[tl * 32 + s]);
                y = fmaf(h[s], sBC[tl * 32 + 16 + s], y);
            }
            float yv = y + uv * dsk;
            float z = g_uz[(size_t)(rowbase + tl) * (2 * EE) + EE + e];
            split_store(yv * siluf(z), g_ah, g_al, off);
        }
    } else {
        for (int tl = 0; tl < CLEN; tl++) {
            size_t off = (size_t)(rowbase + tl) * EE + e;
            float dv = g_delta[off];
            float uv = g_u[off];
            float du = dv * uv;
            float y = 0.f;
            #pragma unroll
            for (int s = 0; s < SS; s++) {
                float dA = __expf(-dv * cs[s]);
                h[s] = fmaf(dA, h[s], du * sBC[tl * 32 + s]);
                y = fmaf(h[s], sBC[tl * 32 + 16 + s], y);
            }
            float yv = y + uv * dsk;
            float z = g_uz[(size_t)(rowbase + tl) * (2 * EE) + EE + e];
            split_store(yv * siluf(z), g_ah, g_al, off);
        }
    }
}

// ------------------- wbar = mean_s W_rw + mean b_rw -----------------------
__global__ void k_wbar(const float* __restrict__ W_rw_l, const float* __restrict__ b_rw_l) {
    int d = blockIdx.x * 256 + threadIdx.x;
    if (d < DD) {
        float s = 0.f;
        #pragma unroll
        for (int j = 0; j < SS; j++) s += W_rw_l[d * SS + j];
        g_wbar[d] = s * (1.f / SS);
    }
    if (blockIdx.x == 0 && threadIdx.x == 0) {
        float bb = 0.f;
        #pragma unroll
        for (int s = 0; s < SS; s++) bb += b_rw_l[s];
        g_wbar[DD] = bb * (1.f / SS);
    }
}

// ------------------- launch -----------------------------------------------
extern "C" void kernel_launch(void* const* d_in, const int* in_sizes, int n_in,
                              void* d_out, int out_size) {
    const int*   x      = (const int*)d_in[0];
    const float* mask   = (const float*)d_in[1];
    const float* emb    = (const float*)d_in[2];
    const float* norm_w = (const float*)d_in[3];
    const float* W_in   = (const float*)d_in[4];
    const float* conv_w = (const float*)d_in[5];
    const float* conv_b = (const float*)d_in[6];
    const float* W_x    = (const float*)d_in[7];
    const float* W_dt   = (const float*)d_in[8];
    const float* b_dt   = (const float*)d_in[9];
    const float* A_log  = (const float*)d_in[10];
    const float* D_skip = (const float*)d_in[11];
    const float* W_out  = (const float*)d_in[12];
    const float* W_rw   = (const float*)d_in[13];
    const float* b_rw   = (const float*)d_in[14];
    const float* ln_g   = (const float*)d_in[15];
    const float* ln_b   = (const float*)d_in[16];
    const float* head_W = (const float*)d_in[17];
    float* out = (float*)d_out;

    float *ph, *puz, *pdbc, *pdelta;
    __nv_bfloat16 *pah, *pal, *pbh, *pbl;
    cudaGetSymbolAddress((void**)&ph,     g_h);
    cudaGetSymbolAddress((void**)&puz,    g_uz);
    cudaGetSymbolAddress((void**)&pdbc,   g_dbc);
    cudaGetSymbolAddress((void**)&pdelta, g_delta);
    cudaGetSymbolAddress((void**)&pah,    g_ah);
    cudaGetSymbolAddress((void**)&pal,    g_al);
    cudaGetSymbolAddress((void**)&pbh,    g_bh);
    cudaGetSymbolAddress((void**)&pbl,    g_bl);

    cudaFuncSetAttribute(tc_gemm<0>, cudaFuncAttributeMaxDynamicSharedMemorySize, TG_SMEM);
    cudaFuncSetAttribute(tc_gemm<1>, cudaFuncAttributeMaxDynamicSharedMemorySize, TG_SMEM);
    cudaFuncSetAttribute(tc_gemm<2>, cudaFuncAttributeMaxDynamicSharedMemorySize, TG_SMEM);
    cudaFuncSetAttribute(tc_gemm<3>, cudaFuncAttributeMaxDynamicSharedMemorySize, TG_SMEM);

    dim3 cvtb(32, 8);

    k_embed<<<(MROWS * DD + 255) / 256, 256>>>(x, mask, emb);

    for (int l = 0; l < NLAYER; l++) {
        if (l == 0)
            k_rms_split<<<MROWS, 256>>>(norm_w);
        else
            k_rw_rms<<<MROWS, 256>>>(norm_w + l * DD);   // applies prev layer's rw too

        // uz = xn @ W_in   (2048x1024 @ 1024x4096)
        k_cvt_wT<<<dim3((2 * EE + 31) / 32, (DD + 31) / 32), cvtb>>>(
            W_in + (size_t)l * DD * 2 * EE, DD, 2 * EE, pbh, pbl);
        tc_gemm<0><<<dim3(2 * EE / 128, MROWS / 128, 1), 256, TG_SMEM>>>(
            pah, pal, pbh, pbl, puz, 2 * EE, MROWS, 2 * EE, DD, nullptr);

        k_conv_split<<<(MROWS * EE + 255) / 256, 256>>>(conv_w + l * EE * 4, conv_b + l * EE);

        // dbc = u @ W_x   (split-K 8, atomic accumulate)
        k_cvt_wT<<<dim3((DBCW + 31) / 32, (EE + 31) / 32), cvtb>>>(
            W_x + (size_t)l * EE * DBCW, EE, DBCW, pbh, pbl);
        k_zero<<<(MROWS * DBCW + 255) / 256, 256>>>(pdbc, MROWS * DBCW);
        tc_gemm<3><<<dim3(1, MROWS / 128, 8), 256, TG_SMEM>>>(
            pah, pal, pbh, pbl, pdbc, DBCW, MROWS, DBCW, EE, nullptr);

        // delta = softplus(dr @ W_dt + b_dt)
        k_cvt_act<<<(MROWS * RR + 255) / 256, 256>>>(pdbc, MROWS, RR, DBCW, pah, pal);
        k_cvt_wT<<<dim3((EE + 31) / 32, (RR + 31) / 32), cvtb>>>(
            W_dt + (size_t)l * RR * EE, RR, EE, pbh, pbl);
        tc_gemm<2><<<dim3(EE / 128, MROWS / 128, 1), 256, TG_SMEM>>>(
            pah, pal, pbh, pbl, pdelta, EE, MROWS, EE, RR, b_dt + l * EE);

        k_scanA2<<<dim3(NCHUNK, EE / 128, BB), 128>>>(A_log + (size_t)l * EE * SS);
        k_scanB<<<(BB * EE + 255) / 256, 256>>>();
        k_scanC2<<<dim3(NCHUNK, EE / 128, BB), 128>>>(A_log + (size_t)l * EE * SS,
                                                      D_skip + l * EE);

        // h += gate @ W_out
        k_cvt_wT<<<dim3((DD + 31) / 32, (EE + 31) / 32), cvtb>>>(
            W_out + (size_t)l * EE * DD, EE, DD, pbh, pbl);
        tc_gemm<1><<<dim3(DD / 128, MROWS / 128, 1), 256, TG_SMEM>>>(
            pah, pal, pbh, pbl, ph, DD, MROWS, DD, EE, nullptr);

        k_wbar<<<(DD + 255) / 256, 256>>>(W_rw + (size_t)l * DD * SS, b_rw + l * SS);
    }

    k_rw_ln<<<MROWS, 256>>>(ln_g, ln_b);

    // logits = xn @ head_W  (2048x1024 @ 1024x32000)
    k_cvt_wT<<<dim3((VV + 31) / 32, (DD + 31) / 32), cvtb>>>(head_W, DD, VV, pbh, pbl);
    tc_gemm<0><<<dim3(VV / 128, MROWS / 128, 1), 256, TG_SMEM>>>(
        pah, pal, pbh, pbl, out, VV, MROWS, VV, DD, nullptr);
}

// round 8
// speedup vs baseline: 4.1935x; 1.1307x over previous
#include <cuda_runtime.h>
#include <cuda_bf16.h>
#include <math.h>
#include <stdint.h>

#define BB 2
#define LL 1024
#define DD 1024
#define EE 2048
#define SS 16
#define RR 64
#define NLAYER 4
#define VV 32000
#define MROWS (BB*LL)
#define NCHUNK 16
#define CLEN (LL/NCHUNK)
#define DBCW 96

// ------------------- scratch (static device globals, no allocs) -------------
__device__ float g_h[MROWS*DD];
__device__ float g_uz[MROWS*2*EE];
__device__ float g_u[MROWS*EE];
__device__ float g_dbc[MROWS*DBCW];
__device__ float g_delta[MROWS*EE];
__device__ float g_P[NCHUNK*BB*EE*SS];
__device__ float g_hend[NCHUNK*BB*EE*SS];
__device__ float g_h0c[NCHUNK*BB*EE*SS];
__device__ float g_wbar[DD+1];

// bf16 hi/lo split operand buffers (16-byte aligned)
__device__ __align__(16) __nv_bfloat16 g_ah[MROWS*EE];
__device__ __align__(16) __nv_bfloat16 g_al[MROWS*EE];
__device__ __align__(16) __nv_bfloat16 g_bh[(size_t)VV*DD];
__device__ __align__(16) __nv_bfloat16 g_bl[(size_t)VV*DD];

__device__ __forceinline__ float siluf(float x) { return x / (1.f + __expf(-x)); }
__device__ __forceinline__ float softplusf(float x) {
    return (x > 20.f) ? x : log1pf(__expf(x));
}
__device__ __forceinline__ void split_store(float x, __nv_bfloat16* h, __nv_bfloat16* l,
                                            size_t idx) {
    __nv_bfloat16 hh = __float2bfloat16(x);
    h[idx] = hh;
    l[idx] = __float2bfloat16(x - __bfloat162float(hh));
}

// ------------------- conversions ------------------------------------------
__global__ void k_cvt_act(const float* __restrict__ A, int M, int K, int lda,
                          __nv_bfloat16* __restrict__ h, __nv_bfloat16* __restrict__ l) {
    int idx = blockIdx.x * 256 + threadIdx.x;
    if (idx >= M * K) return;
    int r = idx / K, c = idx - r * K;
    split_store(A[(size_t)r * lda + c], h, l, idx);
}

// weights: fp32 [K,N] row-major -> transposed bf16 hi/lo [N,K]
__global__ void k_cvt_wT(const float* __restrict__ W, int K, int N,
                         __nv_bfloat16* __restrict__ th, __nv_bfloat16* __restrict__ tl) {
    __shared__ float t[32][33];
    int n0 = blockIdx.x * 32, k0 = blockIdx.y * 32;
    int tx = threadIdx.x, ty = threadIdx.y;
    #pragma unroll
    for (int j = 0; j < 32; j += 8) {
        int k = k0 + ty + j, n = n0 + tx;
        t[ty + j][tx] = (k < K && n < N) ? W[(size_t)k * N + n] : 0.f;
    }
    __syncthreads();
    #pragma unroll
    for (int j = 0; j < 32; j += 8) {
        int n = n0 + ty + j, k = k0 + tx;
        if (n < N && k < K)
            split_store(t[tx][ty + j], th, tl, (size_t)n * K + k);
    }
}

__global__ void k_zero(float* p, int n) {
    int idx = blockIdx.x * 256 + threadIdx.x;
    if (idx < n) p[idx] = 0.f;
}

// ------------------- bf16-split HMMA GEMM ---------------------------------
__device__ __forceinline__ uint32_t smem_u32(const void* p) {
    uint32_t a;
    asm("{ .reg .u64 t; cvta.to.shared.u64 t, %1; cvt.u32.u64 %0, t; }" : "=r"(a) : "l"(p));
    return a;
}
__device__ __forceinline__ void cpa16(uint32_t s, const void* g, bool v) {
    asm volatile("cp.async.cg.shared.global [%0], [%1], 16, %2;"
                 :: "r"(s), "l"(g), "r"(v ? 16 : 0));
}
// swizzled byte offset within one [128 rows][128B] tile
__device__ __forceinline__ uint32_t swz128(int row, int kb) {
    return (uint32_t)(row * 128 + ((((kb >> 4) ^ (row & 7))) << 4) + (kb & 15));
}
#define LDMX4(r, ad) \
    asm volatile("ldmatrix.sync.aligned.m8n8.x4.shared.b16 {%0,%1,%2,%3}, [%4];" \
                 : "=r"((r)[0]), "=r"((r)[1]), "=r"((r)[2]), "=r"((r)[3]) : "r"(ad))
#define MMA16(d, a, b) \
    asm volatile("mma.sync.aligned.m16n8k16.row.col.f32.bf16.bf16.f32 " \
                 "{%0,%1,%2,%3},{%4,%5,%6,%7},{%8,%9},{%0,%1,%2,%3};" \
                 : "+f"((d)[0]), "+f"((d)[1]), "+f"((d)[2]), "+f"((d)[3]) \
                 : "r"((a)[0]), "r"((a)[1]), "r"((a)[2]), "r"((a)[3]), \
                   "r"((b)[0]), "r"((b)[1]))

// 3 stages x 64KB (4 subtiles x 128 rows x 128B)
#define TG_SMEM (3 * 65536)
#define T_AH 0
#define T_AL 16384
#define T_BH 32768
#define T_BL 49152

// MODE: 0 store, 1 C+=AB, 2 softplus(AB+bias), 3 atomicAdd (split-K via blockIdx.z)
// grid: x = M-tile, y = N-tile (consecutive CTAs share B -> L2 reuse)
template<int MODE>
__global__ __launch_bounds__(256)
void tc_gemm(const __nv_bfloat16* __restrict__ Ah, const __nv_bfloat16* __restrict__ Al,
             const __nv_bfloat16* __restrict__ Bh, const __nv_bfloat16* __restrict__ Bl,
             float* __restrict__ C, int ldc, int M, int N, int K,
             const float* __restrict__ bias)
{
    extern __shared__ char smem[];
    uint32_t sb = smem_u32(smem);
    int tid = threadIdx.x, lane = tid & 31, warp = tid >> 5;
    int wm = warp & 1, wn = warp >> 1;
    int bm = blockIdx.x * 128, bn = blockIdx.y * 128;
    int kn = K / gridDim.z;
    int t0 = (blockIdx.z * kn) >> 6, tn = kn >> 6;   // k-tiles of 64

    float acc[4][4][4];
    #pragma unroll
    for (int i = 0; i < 4; i++)
        #pragma unroll
        for (int j = 0; j < 4; j++)
            #pragma unroll
            for (int q = 0; q < 4; q++) acc[i][j][q] = 0.f;

    auto load_stage = [&](int kt, int stg) {
        int k0 = kt << 6;
        uint32_t sbase = sb + stg * 65536;
        #pragma unroll
        for (int i = 0; i < 4; i++) {
            int idx = tid + i * 256;          // 0..1023
            int row = idx >> 3, ch = idx & 7; // 16B chunk
            uint32_t so = (uint32_t)(row * 128 + ((ch ^ (row & 7)) << 4));
            size_t ga = (size_t)(bm + row) * K + k0 + ch * 8;
            cpa16(sbase + T_AH + so, Ah + ga, true);
            cpa16(sbase + T_AL + so, Al + ga, true);
            bool bv = (bn + row) < N;
            size_t gb = bv ? ((size_t)(bn + row) * K + k0 + ch * 8) : 0;
            cpa16(sbase + T_BH + so, Bh + gb, bv);
            cpa16(sbase + T_BL + so, Bl + gb, bv);
        }
        asm volatile("cp.async.commit_group;");
    };

    // fragment double buffers
    uint32_t ahf[2][4][4], alf[2][4][4], bhf[2][2][4], blf[2][2][4];

    auto ldfrag = [&](uint32_t base, int ks, int b) {
        #pragma unroll
        for (int ii = 0; ii < 4; ii++) {
            int row = wm * 64 + ii * 16 + (lane & 15);
            int kb = ks * 32 + ((lane >> 4) << 4);
            uint32_t off = swz128(row, kb);
            LDMX4(ahf[b][ii], base + T_AH + off);
            LDMX4(alf[b][ii], base + T_AL + off);
        }
        #pragma unroll
        for (int jj = 0; jj < 2; jj++) {
            int g = lane >> 3, rr = lane & 7;
            int n = wn * 32 + jj * 16 + ((g >> 1) << 3) + rr;
            int kb = ks * 32 + ((g & 1) << 4);
            uint32_t off = swz128(n, kb);
            LDMX4(bhf[b][jj], base + T_BH + off);
            LDMX4(blf[b][jj], base + T_BL + off);
        }
    };

    // prologue: 2 stages in flight
    load_stage(t0, 0);
    if (tn > 1) load_stage(t0 + 1, 1);
    else asm volatile("cp.async.commit_group;");

    for (int i = 0; i < tn; i++) {
        asm volatile("cp.async.wait_group 1;");
        __syncthreads();
        if (i + 2 < tn) load_stage(t0 + i + 2, (i + 2) % 3);
        else asm volatile("cp.async.commit_group;");

        uint32_t base = sb + (i % 3) * 65536;
        ldfrag(base, 0, 0);
        #pragma unroll
        for (int ks = 0; ks < 4; ks++) {
            int cb = ks & 1;
            if (ks < 3) ldfrag(base, ks + 1, cb ^ 1);
            #pragma unroll
            for (int ii = 0; ii < 4; ii++)
                #pragma unroll
                for (int j = 0; j < 4; j++) {
                    uint32_t* bhp = &bhf[cb][j >> 1][(j & 1) * 2];
                    uint32_t* blp = &blf[cb][j >> 1][(j & 1) * 2];
                    MMA16(acc[ii][j], ahf[cb][ii], bhp);
                    MMA16(acc[ii][j], ahf[cb][ii], blp);
                    MMA16(acc[ii][j], alf[cb][ii], bhp);
                }
        }
    }

    #pragma unroll
    for (int i = 0; i < 4; i++) {
        int r0 = bm + wm * 64 + i * 16 + (lane >> 2);
        #pragma unroll
        for (int j = 0; j < 4; j++) {
            int c = bn + wn * 32 + j * 8 + (lane & 3) * 2;
            if (c >= N) continue;
            #pragma unroll
            for (int half = 0; half < 2; half++) {
                int r = r0 + half * 8;
                float v0 = acc[i][j][half * 2], v1 = acc[i][j][half * 2 + 1];
                float* cp = C + (size_t)r * ldc + c;
                if (MODE == 3) {
                    atomicAdd(cp, v0); atomicAdd(cp + 1, v1);
                } else {
                    if (MODE == 1) {
                        float2 old = *(float2*)cp;
                        v0 += old.x; v1 += old.y;
                    } else if (MODE == 2) {
                        v0 = softplusf(v0 + bias[c]);
                        v1 = softplusf(v1 + bias[c + 1]);
                    }
                    *(float2*)cp = make_float2(v0, v1);
                }
            }
        }
    }
}

// ------------------- embed ------------------------------------------------
__global__ void k_embed(const int* __restrict__ x, const float* __restrict__ mask,
                        const float* __restrict__ emb) {
    int idx = blockIdx.x * 256 + threadIdx.x;
    if (idx >= MROWS * DD) return;
    int row = idx >> 10;
    int d = idx & 1023;
    g_h[idx] = emb[(size_t)x[row] * DD + d] * mask[row];
}

// ------------------- rmsnorm (layer 0) -> split bf16 ----------------------
__global__ void k_rms_split(const float* __restrict__ w) {
    int row = blockIdx.x;
    const float* hr = g_h + (size_t)row * DD;
    float ss = 0.f;
    for (int d = threadIdx.x; d < DD; d += 256) { float v = hr[d]; ss += v * v; }
    __shared__ float red[256];
    red[threadIdx.x] = ss; __syncthreads();
    for (int st = 128; st > 0; st >>= 1) {
        if (threadIdx.x < st) red[threadIdx.x] += red[threadIdx.x + st];
        __syncthreads();
    }
    float scale = rsqrtf(red[0] / DD + 1e-5f);
    for (int d = threadIdx.x; d < DD; d += 256)
        split_store(hr[d] * scale * w[d], g_ah, g_al, (size_t)row * DD + d);
}

// ------------------- fused rw-scale + rmsnorm -> split --------------------
__global__ void k_rw_rms(const float* __restrict__ w) {
    int row = blockIdx.x;
    float* hr = g_h + (size_t)row * DD;
    float dot = 0.f, ss = 0.f;
    for (int d = threadIdx.x; d < DD; d += 256) {
        float v = hr[d];
        dot += v * g_wbar[d];
        ss += v * v;
    }
    __shared__ float r1[256], r2[256];
    r1[threadIdx.x] = dot; r2[threadIdx.x] = ss; __syncthreads();
    for (int st = 128; st > 0; st >>= 1) {
        if (threadIdx.x < st) {
            r1[threadIdx.x] += r1[threadIdx.x + st];
            r2[threadIdx.x] += r2[threadIdx.x + st];
        }
        __syncthreads();
    }
    float scale = r1[0] + g_wbar[DD];
    float inv = rsqrtf(scale * scale * r2[0] / DD + 1e-5f);
    for (int d = threadIdx.x; d < DD; d += 256) {
        float hv = hr[d] * scale;
        hr[d] = hv;
        split_store(hv * inv * w[d], g_ah, g_al, (size_t)row * DD + d);
    }
}

// ------------------- fused rw-scale + layernorm -> split ------------------
__global__ void k_rw_ln(const float* __restrict__ gam, const float* __restrict__ bet) {
    int row = blockIdx.x;
    const float* hr = g_h + (size_t)row * DD;
    float dot = 0.f, ss = 0.f, sum = 0.f;
    for (int d = threadIdx.x; d < DD; d += 256) {
        float v = hr[d];
        dot += v * g_wbar[d];
        ss += v * v;
        sum += v;
    }
    __shared__ float r1[256], r2[256], r3[256];
    r1[threadIdx.x] = dot; r2[threadIdx.x] = ss; r3[threadIdx.x] = sum; __syncthreads();
    for (int st = 128; st > 0; st >>= 1) {
        if (threadIdx.x < st) {
            r1[threadIdx.x] += r1[threadIdx.x + st];
            r2[threadIdx.x] += r2[threadIdx.x + st];
            r3[threadIdx.x] += r3[threadIdx.x + st];
        }
        __syncthreads();
    }
    float scale = r1[0] + g_wbar[DD];
    float mean = scale * r3[0] / DD;
    float var = scale * scale * r2[0] / DD - mean * mean;
    float inv = rsqrtf(var + 1e-5f);
    for (int d = threadIdx.x; d < DD; d += 256) {
        float hv = hr[d] * scale;
        split_store((hv - mean) * inv * gam[d] + bet[d], g_ah, g_al, (size_t)row * DD + d);
    }
}

// ------------------- causal dwconv + silu -> u fp32 + split ---------------
__global__ void k_conv_split(const float* __restrict__ cw, const float* __restrict__ cb) {
    int idx = blockIdx.x * 256 + threadIdx.x;
    if (idx >= MROWS * EE) return;
    int row = idx >> 11;
    int e = idx & (EE - 1);
    int b = row >> 10;
    int l = row & 1023;
    float acc = cb[e];
    #pragma unroll
    for (int k = 0; k < 4; k++) {
        int l2 = l - 3 + k;
        if (l2 >= 0)
            acc += g_uz[(size_t)(b * LL + l2) * (2 * EE) + e] * cw[e * 4 + k];
    }
    float u = siluf(acc);
    g_u[idx] = u;
    split_store(u, g_ah, g_al, idx);
}

// ------------------- selective scan (integer-power fast path) -------------
__global__ void k_scanA2(const float* __restrict__ A_log_l) {
    int c = blockIdx.x, eg = blockIdx.y, b = blockIdx.z;
    int e = eg * 128 + threadIdx.x;
    __shared__ float sB[CLEN * 16];
    for (int i = threadIdx.x; i < CLEN * 16; i += 128) {
        int tl = i >> 4, j = i & 15;
        sB[i] = g_dbc[(size_t)(b * LL + c * CLEN + tl) * DBCW + RR + j];
    }
    __syncthreads();
    float cs[SS];
    bool consec = true;
    #pragma unroll
    for (int s = 0; s < SS; s++) {
        cs[s] = __expf(A_log_l[e * SS + s]);
        consec = consec && (fabsf(cs[s] - (float)(s + 1)) < 1e-4f);
    }
    float h[SS];
    #pragma unroll
    for (int s = 0; s < SS; s++) h[s] = 0.f;
    float dsum = 0.f;
    int rowbase = b * LL + c * CLEN;
    if (consec) {
        for (int tl = 0; tl < CLEN; tl++) {
            size_t off = (size_t)(rowbase + tl) * EE + e;
            float dv = g_delta[off];
            float du = dv * g_u[off];
            dsum += dv;
            float q = __expf(-dv), p = 1.f;
            #pragma unroll
            for (int s = 0; s < SS; s++) {
                p *= q;
                h[s] = fmaf(p, h[s], du * sB[tl * 16 + s]);
            }
        }
    } else {
        for (int tl = 0; tl < CLEN; tl++) {
            size_t off = (size_t)(rowbase + tl) * EE + e;
            float dv = g_delta[off];
            float du = dv * g_u[off];
            dsum += dv;
            #pragma unroll
            for (int s = 0; s < SS; s++) {
                float dA = __expf(-dv * cs[s]);
                h[s] = fmaf(dA, h[s], du * sB[tl * 16 + s]);
            }
        }
    }
    float P[SS];
    if (consec) {
        float Q = __expf(-dsum), p = 1.f;
        #pragma unroll
        for (int s = 0; s < SS; s++) { p *= Q; P[s] = p; }
    } else {
        #pragma unroll
        for (int s = 0; s < SS; s++) P[s] = __expf(-dsum * cs[s]);
    }
    size_t base = ((size_t)c * BB * EE + b * EE + e) * SS;
    float4* Pp = (float4*)(g_P + base);
    float4* Hp = (float4*)(g_hend + base);
    #pragma unroll
    for (int q = 0; q < 4; q++) {
        Pp[q] = make_float4(P[q*4], P[q*4+1], P[q*4+2], P[q*4+3]);
        Hp[q] = make_float4(h[q*4], h[q*4+1], h[q*4+2], h[q*4+3]);
    }
}

__global__ void k_scanB() {
    int idx = blockIdx.x * 256 + threadIdx.x;
    if (idx >= BB * EE) return;
    float h[SS];
    #pragma unroll
    for (int s = 0; s < SS; s++) h[s] = 0.f;
    for (int c = 0; c < NCHUNK; c++) {
        size_t base = ((size_t)c * BB * EE + idx) * SS;
        float4* H0 = (float4*)(g_h0c + base);
        const float4* Pp = (const float4*)(g_P + base);
        const float4* He = (const float4*)(g_hend + base);
        #pragma unroll
        for (int q = 0; q < 4; q++) {
            H0[q] = make_float4(h[q*4], h[q*4+1], h[q*4+2], h[q*4+3]);
            float4 p = Pp[q], he = He[q];
            h[q*4+0] = fmaf(p.x, h[q*4+0], he.x);
            h[q*4+1] = fmaf(p.y, h[q*4+1], he.y);
            h[q*4+2] = fmaf(p.z, h[q*4+2], he.z);
            h[q*4+3] = fmaf(p.w, h[q*4+3], he.w);
        }
    }
}

// scanC fused with gate: writes gate = (y + u*Dsk) * silu(z) as bf16 split
__global__ void k_scanC2(const float* __restrict__ A_log_l, const float* __restrict__ Dsk) {
    int c = blockIdx.x, eg = blockIdx.y, b = blockIdx.z;
    int e = eg * 128 + threadIdx.x;
    __shared__ float sBC[CLEN * 32];
    for (int i = threadIdx.x; i < CLEN * 32; i += 128) {
        int tl = i >> 5, j = i & 31;
        sBC[i] = g_dbc[(size_t)(b * LL + c * CLEN + tl) * DBCW + RR + j];
    }
    __syncthreads();
    float cs[SS];
    bool consec = true;
    #pragma unroll
    for (int s = 0; s < SS; s++) {
        cs[s] = __expf(A_log_l[e * SS + s]);
        consec = consec && (fabsf(cs[s] - (float)(s + 1)) < 1e-4f);
    }
    float h[SS];
    size_t base = ((size_t)c * BB * EE + b * EE + e) * SS;
    #pragma unroll
    for (int q = 0; q < 4; q++) {
        float4 v = ((const float4*)(g_h0c + base))[q];
        h[q*4+0] = v.x; h[q*4+1] = v.y; h[q*4+2] = v.z; h[q*4+3] = v.w;
    }
    float dsk = Dsk[e];
    int rowbase = b * LL + c * CLEN;
    if (consec) {
        for (int tl = 0; tl < CLEN; tl++) {
            size_t off = (size_t)(rowbase + tl) * EE + e;
            float dv = g_delta[off];
            float uv = g_u[off];
            float du = dv * uv;
            float q = __expf(-dv), p = 1.f, y = 0.f;
            #pragma unroll
            for (int s = 0; s < SS; s++) {
                p *= q;
                h[s] = fmaf(p, h[s], du * sBC[tl * 32 + s]);
                y = fmaf(h[s], sBC[tl * 32 + 16 + s], y);
            }
            float yv = y + uv * dsk;
            float z = g_uz[(size_t)(rowbase + tl) * (2 * EE) + EE + e];
            split_store(yv * siluf(z), g_ah, g_al, off);
        }
    } else {
        for (int tl = 0; tl < CLEN; tl++) {
            size_t off = (size_t)(rowbase + tl) * EE + e;
            float dv = g_delta[off];
            float uv = g_u[off];
            float du = dv * uv;
            float y = 0.f;
            #pragma unroll
            for (int s = 0; s < SS; s++) {
                float dA = __expf(-dv * cs[s]);
                h[s] = fmaf(dA, h[s], du * sBC[tl * 32 + s]);
                y = fmaf(h[s], sBC[tl * 32 + 16 + s], y);
            }
            float yv = y + uv * dsk;
            float z = g_uz[(size_t)(rowbase + tl) * (2 * EE) + EE + e];
            split_store(yv * siluf(z), g_ah, g_al, off);
        }
    }
}

// ------------------- wbar = mean_s W_rw + mean b_rw -----------------------
__global__ void k_wbar(const float* __restrict__ W_rw_l, const float* __restrict__ b_rw_l) {
    int d = blockIdx.x * 256 + threadIdx.x;
    if (d < DD) {
        float s = 0.f;
        #pragma unroll
        for (int j = 0; j < SS; j++) s += W_rw_l[d * SS + j];
        g_wbar[d] = s * (1.f / SS);
    }
    if (blockIdx.x == 0 && threadIdx.x == 0) {
        float bb = 0.f;
        #pragma unroll
        for (int s = 0; s < SS; s++) bb += b_rw_l[s];
        g_wbar[DD] = bb * (1.f / SS);
    }
}

// ------------------- launch -----------------------------------------------
extern "C" void kernel_launch(void* const* d_in, const int* in_sizes, int n_in,
                              void* d_out, int out_size) {
    const int*   x      = (const int*)d_in[0];
    const float* mask   = (const float*)d_in[1];
    const float* emb    = (const float*)d_in[2];
    const float* norm_w = (const float*)d_in[3];
    const float* W_in   = (const float*)d_in[4];
    const float* conv_w = (const float*)d_in[5];
    const float* conv_b = (const float*)d_in[6];
    const float* W_x    = (const float*)d_in[7];
    const float* W_dt   = (const float*)d_in[8];
    const float* b_dt   = (const float*)d_in[9];
    const float* A_log  = (const float*)d_in[10];
    const float* D_skip = (const float*)d_in[11];
    const float* W_out  = (const float*)d_in[12];
    const float* W_rw   = (const float*)d_in[13];
    const float* b_rw   = (const float*)d_in[14];
    const float* ln_g   = (const float*)d_in[15];
    const float* ln_b   = (const float*)d_in[16];
    const float* head_W = (const float*)d_in[17];
    float* out = (float*)d_out;

    float *ph, *puz, *pdbc, *pdelta;
    __nv_bfloat16 *pah, *pal, *pbh, *pbl;
    cudaGetSymbolAddress((void**)&ph,     g_h);
    cudaGetSymbolAddress((void**)&puz,    g_uz);
    cudaGetSymbolAddress((void**)&pdbc,   g_dbc);
    cudaGetSymbolAddress((void**)&pdelta, g_delta);
    cudaGetSymbolAddress((void**)&pah,    g_ah);
    cudaGetSymbolAddress((void**)&pal,    g_al);
    cudaGetSymbolAddress((void**)&pbh,    g_bh);
    cudaGetSymbolAddress((void**)&pbl,    g_bl);

    cudaFuncSetAttribute(tc_gemm<0>, cudaFuncAttributeMaxDynamicSharedMemorySize, TG_SMEM);
    cudaFuncSetAttribute(tc_gemm<1>, cudaFuncAttributeMaxDynamicSharedMemorySize, TG_SMEM);
    cudaFuncSetAttribute(tc_gemm<2>, cudaFuncAttributeMaxDynamicSharedMemorySize, TG_SMEM);
    cudaFuncSetAttribute(tc_gemm<3>, cudaFuncAttributeMaxDynamicSharedMemorySize, TG_SMEM);

    dim3 cvtb(32, 8);

    k_embed<<<(MROWS * DD + 255) / 256, 256>>>(x, mask, emb);

    for (int l = 0; l < NLAYER; l++) {
        if (l == 0)
            k_rms_split<<<MROWS, 256>>>(norm_w);
        else
            k_rw_rms<<<MROWS, 256>>>(norm_w + l * DD);   // applies prev layer's rw too

        // uz = xn @ W_in   (2048x1024 @ 1024x4096)
        k_cvt_wT<<<dim3((2 * EE + 31) / 32, (DD + 31) / 32), cvtb>>>(
            W_in + (size_t)l * DD * 2 * EE, DD, 2 * EE, pbh, pbl);
        tc_gemm<0><<<dim3(MROWS / 128, 2 * EE / 128, 1), 256, TG_SMEM>>>(
            pah, pal, pbh, pbl, puz, 2 * EE, MROWS, 2 * EE, DD, nullptr);

        k_conv_split<<<(MROWS * EE + 255) / 256, 256>>>(conv_w + l * EE * 4, conv_b + l * EE);

        // dbc = u @ W_x   (split-K 8, atomic accumulate)
        k_cvt_wT<<<dim3((DBCW + 31) / 32, (EE + 31) / 32), cvtb>>>(
            W_x + (size_t)l * EE * DBCW, EE, DBCW, pbh, pbl);
        k_zero<<<(MROWS * DBCW + 255) / 256, 256>>>(pdbc, MROWS * DBCW);
        tc_gemm<3><<<dim3(MROWS / 128, 1, 8), 256, TG_SMEM>>>(
            pah, pal, pbh, pbl, pdbc, DBCW, MROWS, DBCW, EE, nullptr);

        // delta = softplus(dr @ W_dt + b_dt)
        k_cvt_act<<<(MROWS * RR + 255) / 256, 256>>>(pdbc, MROWS, RR, DBCW, pah, pal);
        k_cvt_wT<<<dim3((EE + 31) / 32, (RR + 31) / 32), cvtb>>>(
            W_dt + (size_t)l * RR * EE, RR, EE, pbh, pbl);
        tc_gemm<2><<<dim3(MROWS / 128, EE / 128, 1), 256, TG_SMEM>>>(
            pah, pal, pbh, pbl, pdelta, EE, MROWS, EE, RR, b_dt + l * EE);

        k_scanA2<<<dim3(NCHUNK, EE / 128, BB), 128>>>(A_log + (size_t)l * EE * SS);
        k_scanB<<<(BB * EE + 255) / 256, 256>>>();
        k_scanC2<<<dim3(NCHUNK, EE / 128, BB), 128>>>(A_log + (size_t)l * EE * SS,
                                                      D_skip + l * EE);

        // h += gate @ W_out
        k_cvt_wT<<<dim3((DD + 31) / 32, (EE + 31) / 32), cvtb>>>(
            W_out + (size_t)l * EE * DD, EE, DD, pbh, pbl);
        tc_gemm<1><<<dim3(MROWS / 128, DD / 128, 1), 256, TG_SMEM>>>(
            pah, pal, pbh, pbl, ph, DD, MROWS, DD, EE, nullptr);

        k_wbar<<<(DD + 255) / 256, 256>>>(W_rw + (size_t)l * DD * SS, b_rw + l * SS);
    }

    k_rw_ln<<<MROWS, 256>>>(ln_g, ln_b);

    // logits = xn @ head_W  (2048x1024 @ 1024x32000)
    k_cvt_wT<<<dim3((VV + 31) / 32, (DD + 31) / 32), cvtb>>>(head_W, DD, VV, pbh, pbl);
    tc_gemm<0><<<dim3(MROWS / 128, VV / 128, 1), 256, TG_SMEM>>>(
        pah, pal, pbh, pbl, out, VV, MROWS, VV, DD, nullptr);
}

// round 9
// speedup vs baseline: 5.3723x; 1.2811x over previous
#include <cuda_runtime.h>
#include <cuda_bf16.h>
#include <cuda_fp16.h>
#include <math.h>
#include <stdint.h>

#define BB 2
#define LL 1024
#define DD 1024
#define EE 2048
#define SS 16
#define RR 64
#define NLAYER 4
#define VV 32000
#define MROWS (BB*LL)
#define NCHUNK 16
#define CLEN (LL/NCHUNK)
#define DBCW 96

// ------------------- scratch (static device globals, no allocs) -------------
__device__ float g_h[MROWS*DD];
__device__ float g_uz[MROWS*2*EE];
__device__ float g_u[MROWS*EE];
__device__ float g_dbc[MROWS*DBCW];
__device__ float g_delta[MROWS*EE];
__device__ float g_P[NCHUNK*BB*EE*SS];
__device__ float g_hend[NCHUNK*BB*EE*SS];
__device__ float g_h0c[NCHUNK*BB*EE*SS];
__device__ float g_wbar[DD+1];

// bf16 hi/lo split operand buffers (16-byte aligned); g_ah/g_bh reused as fp16
__device__ __align__(16) __nv_bfloat16 g_ah[MROWS*EE];
__device__ __align__(16) __nv_bfloat16 g_al[MROWS*EE];
__device__ __align__(16) __nv_bfloat16 g_bh[(size_t)VV*DD];
__device__ __align__(16) __nv_bfloat16 g_bl[(size_t)VV*DD];

__device__ __forceinline__ float siluf(float x) { return x / (1.f + __expf(-x)); }
__device__ __forceinline__ float softplusf(float x) {
    return (x > 20.f) ? x : log1pf(__expf(x));
}
__device__ __forceinline__ void split_store(float x, __nv_bfloat16* h, __nv_bfloat16* l,
                                            size_t idx) {
    __nv_bfloat16 hh = __float2bfloat16(x);
    h[idx] = hh;
    l[idx] = __float2bfloat16(x - __bfloat162float(hh));
}

// ------------------- conversions ------------------------------------------
__global__ void k_cvt_act(const float* __restrict__ A, int M, int K, int lda,
                          __nv_bfloat16* __restrict__ h, __nv_bfloat16* __restrict__ l) {
    int idx = blockIdx.x * 256 + threadIdx.x;
    if (idx >= M * K) return;
    int r = idx / K, c = idx - r * K;
    split_store(A[(size_t)r * lda + c], h, l, idx);
}

// weights: fp32 [K,N] row-major -> transposed bf16 hi/lo [N,K]
__global__ void k_cvt_wT(const float* __restrict__ W, int K, int N,
                         __nv_bfloat16* __restrict__ th, __nv_bfloat16* __restrict__ tl) {
    __shared__ float t[32][33];
    int n0 = blockIdx.x * 32, k0 = blockIdx.y * 32;
    int tx = threadIdx.x, ty = threadIdx.y;
    #pragma unroll
    for (int j = 0; j < 32; j += 8) {
        int k = k0 + ty + j, n = n0 + tx;
        t[ty + j][tx] = (k < K && n < N) ? W[(size_t)k * N + n] : 0.f;
    }
    __syncthreads();
    #pragma unroll
    for (int j = 0; j < 32; j += 8) {
        int n = n0 + ty + j, k = k0 + tx;
        if (n < N && k < K)
            split_store(t[tx][ty + j], th, tl, (size_t)n * K + k);
    }
}

// weights: fp32 [K,N] -> transposed fp16 [N,K] (head only)
__global__ void k_cvt_wT_f16(const float* __restrict__ W, int K, int N,
                             __half* __restrict__ th) {
    __shared__ float t[32][33];
    int n0 = blockIdx.x * 32, k0 = blockIdx.y * 32;
    int tx = threadIdx.x, ty = threadIdx.y;
    #pragma unroll
    for (int j = 0; j < 32; j += 8) {
        int k = k0 + ty + j, n = n0 + tx;
        t[ty + j][tx] = (k < K && n < N) ? W[(size_t)k * N + n] : 0.f;
    }
    __syncthreads();
    #pragma unroll
    for (int j = 0; j < 32; j += 8) {
        int n = n0 + ty + j, k = k0 + tx;
        if (n < N && k < K)
            th[(size_t)n * K + k] = __float2half(t[tx][ty + j]);
    }
}

__global__ void k_zero(float* p, int n) {
    int idx = blockIdx.x * 256 + threadIdx.x;
    if (idx < n) p[idx] = 0.f;
}

// ------------------- GEMM common ------------------------------------------
__device__ __forceinline__ uint32_t smem_u32(const void* p) {
    uint32_t a;
    asm("{ .reg .u64 t; cvta.to.shared.u64 t, %1; cvt.u32.u64 %0, t; }" : "=r"(a) : "l"(p));
    return a;
}
__device__ __forceinline__ void cpa16(uint32_t s, const void* g, bool v) {
    asm volatile("cp.async.cg.shared.global [%0], [%1], 16, %2;"
                 :: "r"(s), "l"(g), "r"(v ? 16 : 0));
}
__device__ __forceinline__ uint32_t swz128(int row, int kb) {
    return (uint32_t)(row * 128 + ((((kb >> 4) ^ (row & 7))) << 4) + (kb & 15));
}
#define LDMX4(r, ad) \
    asm volatile("ldmatrix.sync.aligned.m8n8.x4.shared.b16 {%0,%1,%2,%3}, [%4];" \
                 : "=r"((r)[0]), "=r"((r)[1]), "=r"((r)[2]), "=r"((r)[3]) : "r"(ad))
#define MMA16(d, a, b) \
    asm volatile("mma.sync.aligned.m16n8k16.row.col.f32.bf16.bf16.f32 " \
                 "{%0,%1,%2,%3},{%4,%5,%6,%7},{%8,%9},{%0,%1,%2,%3};" \
                 : "+f"((d)[0]), "+f"((d)[1]), "+f"((d)[2]), "+f"((d)[3]) \
                 : "r"((a)[0]), "r"((a)[1]), "r"((a)[2]), "r"((a)[3]), \
                   "r"((b)[0]), "r"((b)[1]))
#define MMA16H(d, a, b) \
    asm volatile("mma.sync.aligned.m16n8k16.row.col.f32.f16.f16.f32 " \
                 "{%0,%1,%2,%3},{%4,%5,%6,%7},{%8,%9},{%0,%1,%2,%3};" \
                 : "+f"((d)[0]), "+f"((d)[1]), "+f"((d)[2]), "+f"((d)[3]) \
                 : "r"((a)[0]), "r"((a)[1]), "r"((a)[2]), "r"((a)[3]), \
                   "r"((b)[0]), "r"((b)[1]))

// ------------------- bf16-split 3-pass GEMM (internal layers) -------------
#define TG_SMEM (3 * 65536)
#define T_AH 0
#define T_AL 16384
#define T_BH 32768
#define T_BL 49152

// MODE: 0 store, 1 C+=AB, 2 softplus(AB+bias), 3 atomicAdd (split-K via blockIdx.z)
template<int MODE>
__global__ __launch_bounds__(256)
void tc_gemm(const __nv_bfloat16* __restrict__ Ah, const __nv_bfloat16* __restrict__ Al,
             const __nv_bfloat16* __restrict__ Bh, const __nv_bfloat16* __restrict__ Bl,
             float* __restrict__ C, int ldc, int M, int N, int K,
             const float* __restrict__ bias)
{
    extern __shared__ char smem[];
    uint32_t sb = smem_u32(smem);
    int tid = threadIdx.x, lane = tid & 31, warp = tid >> 5;
    int wm = warp & 1, wn = warp >> 1;
    int bm = blockIdx.x * 128, bn = blockIdx.y * 128;
    int kn = K / gridDim.z;
    int t0 = (blockIdx.z * kn) >> 6, tn = kn >> 6;

    float acc[4][4][4];
    #pragma unroll
    for (int i = 0; i < 4; i++)
        #pragma unroll
        for (int j = 0; j < 4; j++)
            #pragma unroll
            for (int q = 0; q < 4; q++) acc[i][j][q] = 0.f;

    auto load_stage = [&](int kt, int stg) {
        int k0 = kt << 6;
        uint32_t sbase = sb + stg * 65536;
        #pragma unroll
        for (int i = 0; i < 4; i++) {
            int idx = tid + i * 256;
            int row = idx >> 3, ch = idx & 7;
            uint32_t so = (uint32_t)(row * 128 + ((ch ^ (row & 7)) << 4));
            size_t ga = (size_t)(bm + row) * K + k0 + ch * 8;
            cpa16(sbase + T_AH + so, Ah + ga, true);
            cpa16(sbase + T_AL + so, Al + ga, true);
            bool bv = (bn + row) < N;
            size_t gb = bv ? ((size_t)(bn + row) * K + k0 + ch * 8) : 0;
            cpa16(sbase + T_BH + so, Bh + gb, bv);
            cpa16(sbase + T_BL + so, Bl + gb, bv);
        }
        asm volatile("cp.async.commit_group;");
    };

    uint32_t ahf[2][4][4], alf[2][4][4], bhf[2][2][4], blf[2][2][4];

    auto ldfrag = [&](uint32_t base, int ks, int b) {
        #pragma unroll
        for (int ii = 0; ii < 4; ii++) {
            int row = wm * 64 + ii * 16 + (lane & 15);
            int kb = ks * 32 + ((lane >> 4) << 4);
            uint32_t off = swz128(row, kb);
            LDMX4(ahf[b][ii], base + T_AH + off);
            LDMX4(alf[b][ii], base + T_AL + off);
        }
        #pragma unroll
        for (int jj = 0; jj < 2; jj++) {
            int g = lane >> 3, rr = lane & 7;
            int n = wn * 32 + jj * 16 + ((g >> 1) << 3) + rr;
            int kb = ks * 32 + ((g & 1) << 4);
            uint32_t off = swz128(n, kb);
            LDMX4(bhf[b][jj], base + T_BH + off);
            LDMX4(blf[b][jj], base + T_BL + off);
        }
    };

    load_stage(t0, 0);
    if (tn > 1) load_stage(t0 + 1, 1);
    else asm volatile("cp.async.commit_group;");

    for (int i = 0; i < tn; i++) {
        asm volatile("cp.async.wait_group 1;");
        __syncthreads();
        if (i + 2 < tn) load_stage(t0 + i + 2, (i + 2) % 3);
        else asm volatile("cp.async.commit_group;");

        uint32_t base = sb + (i % 3) * 65536;
        ldfrag(base, 0, 0);
        #pragma unroll
        for (int ks = 0; ks < 4; ks++) {
            int cb = ks & 1;
            if (ks < 3) ldfrag(base, ks + 1, cb ^ 1);
            #pragma unroll
            for (int ii = 0; ii < 4; ii++)
                #pragma unroll
                for (int j = 0; j < 4; j++) {
                    uint32_t* bhp = &bhf[cb][j >> 1][(j & 1) * 2];
                    uint32_t* blp = &blf[cb][j >> 1][(j & 1) * 2];
                    MMA16(acc[ii][j], ahf[cb][ii], bhp);
                    MMA16(acc[ii][j], ahf[cb][ii], blp);
                    MMA16(acc[ii][j], alf[cb][ii], bhp);
                }
        }
    }

    #pragma unroll
    for (int i = 0; i < 4; i++) {
        int r0 = bm + wm * 64 + i * 16 + (lane >> 2);
        #pragma unroll
        for (int j = 0; j < 4; j++) {
            int c = bn + wn * 32 + j * 8 + (lane & 3) * 2;
            if (c >= N) continue;
            #pragma unroll
            for (int half = 0; half < 2; half++) {
                int r = r0 + half * 8;
                float v0 = acc[i][j][half * 2], v1 = acc[i][j][half * 2 + 1];
                float* cp = C + (size_t)r * ldc + c;
                if (MODE == 3) {
                    atomicAdd(cp, v0); atomicAdd(cp + 1, v1);
                } else {
                    if (MODE == 1) {
                        float2 old = *(float2*)cp;
                        v0 += old.x; v1 += old.y;
                    } else if (MODE == 2) {
                        v0 = softplusf(v0 + bias[c]);
                        v1 = softplusf(v1 + bias[c + 1]);
                    }
                    *(float2*)cp = make_float2(v0, v1);
                }
            }
        }
    }
}

// ------------------- fp16 single-pass GEMM (head) -------------------------
// 96KB smem (3 stages x 32KB), <=128 regs -> 2 CTAs/SM
#define TG1_SMEM (3 * 32768)
__global__ __launch_bounds__(256, 2)
void tc_gemm1(const __half* __restrict__ A, const __half* __restrict__ Bp,
              float* __restrict__ C, int ldc, int M, int N, int K)
{
    extern __shared__ char smem[];
    uint32_t sb = smem_u32(smem);
    int tid = threadIdx.x, lane = tid & 31, warp = tid >> 5;
    int wm = warp & 1, wn = warp >> 1;
    int bm = blockIdx.x * 128, bn = blockIdx.y * 128;
    int tn = K >> 6;

    float acc[4][4][4];
    #pragma unroll
    for (int i = 0; i < 4; i++)
        #pragma unroll
        for (int j = 0; j < 4; j++)
            #pragma unroll
            for (int q = 0; q < 4; q++) acc[i][j][q] = 0.f;

    auto load_stage = [&](int kt, int stg) {
        int k0 = kt << 6;
        uint32_t sbase = sb + stg * 32768;
        #pragma unroll
        for (int i = 0; i < 4; i++) {
            int idx = tid + i * 256;           // 0..1023
            int half_sel = idx >> 9;           // 0 = A, 1 = B
            int sub = idx & 511;
            int row = sub >> 2, ch = (sub & 3) << 1;  // two 16B chunks
            uint32_t so = (uint32_t)(row * 128 + ((ch ^ (row & 7)) << 4));
            uint32_t so2 = (uint32_t)(row * 128 + (((ch + 1) ^ (row & 7)) << 4));
            if (half_sel == 0) {
                size_t ga = (size_t)(bm + row) * K + k0 + ch * 8;
                cpa16(sbase + so, A + ga, true);
                cpa16(sbase + so2, A + ga + 8, true);
            } else {
                bool bv = (bn + row) < N;
                size_t gb = bv ? ((size_t)(bn + row) * K + k0 + ch * 8) : 0;
                cpa16(sbase + 16384 + so, Bp + gb, bv);
                cpa16(sbase + 16384 + so2, Bp + gb + 8, bv);
            }
        }
        asm volatile("cp.async.commit_group;");
    };

    load_stage(0, 0);
    if (tn > 1) load_stage(1, 1);
    else asm volatile("cp.async.commit_group;");

    for (int i = 0; i < tn; i++) {
        asm volatile("cp.async.wait_group 1;");
        __syncthreads();
        if (i + 2 < tn) load_stage(i + 2, (i + 2) % 3);
        else asm volatile("cp.async.commit_group;");

        uint32_t base = sb + (i % 3) * 32768;
        #pragma unroll
        for (int ks = 0; ks < 4; ks++) {
            uint32_t af[4][4], bf[2][4];
            #pragma unroll
            for (int ii = 0; ii < 4; ii++) {
                int row = wm * 64 + ii * 16 + (lane & 15);
                int kb = ks * 32 + ((lane >> 4) << 4);
                LDMX4(af[ii], base + swz128(row, kb));
            }
            #pragma unroll
            for (int jj = 0; jj < 2; jj++) {
                int g = lane >> 3, rr = lane & 7;
                int n = wn * 32 + jj * 16 + ((g >> 1) << 3) + rr;
                int kb = ks * 32 + ((g & 1) << 4);
                LDMX4(bf[jj], base + 16384 + swz128(n, kb));
            }
            #pragma unroll
            for (int ii = 0; ii < 4; ii++)
                #pragma unroll
                for (int j = 0; j < 4; j++)
                    MMA16H(acc[ii][j], af[ii], &bf[j >> 1][(j & 1) * 2]);
        }
    }

    #pragma unroll
    for (int i = 0; i < 4; i++) {
        int r0 = bm + wm * 64 + i * 16 + (lane >> 2);
        #pragma unroll
        for (int j = 0; j < 4; j++) {
            int c = bn + wn * 32 + j * 8 + (lane & 3) * 2;
            if (c >= N) continue;
            #pragma unroll
            for (int half = 0; half < 2; half++) {
                int r = r0 + half * 8;
                *(float2*)(C + (size_t)r * ldc + c) =
                    make_float2(acc[i][j][half * 2], acc[i][j][half * 2 + 1]);
            }
        }
    }
}

// ------------------- embed ------------------------------------------------
__global__ void k_embed(const int* __restrict__ x, const float* __restrict__ mask,
                        const float* __restrict__ emb) {
    int idx = blockIdx.x * 256 + threadIdx.x;
    if (idx >= MROWS * DD) return;
    int row = idx >> 10;
    int d = idx & 1023;
    g_h[idx] = emb[(size_t)x[row] * DD + d] * mask[row];
}

// ------------------- rmsnorm (layer 0) -> split bf16 ----------------------
__global__ void k_rms_split(const float* __restrict__ w) {
    int row = blockIdx.x;
    const float* hr = g_h + (size_t)row * DD;
    float ss = 0.f;
    for (int d = threadIdx.x; d < DD; d += 256) { float v = hr[d]; ss += v * v; }
    __shared__ float red[256];
    red[threadIdx.x] = ss; __syncthreads();
    for (int st = 128; st > 0; st >>= 1) {
        if (threadIdx.x < st) red[threadIdx.x] += red[threadIdx.x + st];
        __syncthreads();
    }
    float scale = rsqrtf(red[0] / DD + 1e-5f);
    for (int d = threadIdx.x; d < DD; d += 256)
        split_store(hr[d] * scale * w[d], g_ah, g_al, (size_t)row * DD + d);
}

// ------------------- fused rw-scale + rmsnorm -> split --------------------
__global__ void k_rw_rms(const float* __restrict__ w) {
    int row = blockIdx.x;
    float* hr = g_h + (size_t)row * DD;
    float dot = 0.f, ss = 0.f;
    for (int d = threadIdx.x; d < DD; d += 256) {
        float v = hr[d];
        dot += v * g_wbar[d];
        ss += v * v;
    }
    __shared__ float r1[256], r2[256];
    r1[threadIdx.x] = dot; r2[threadIdx.x] = ss; __syncthreads();
    for (int st = 128; st > 0; st >>= 1) {
        if (threadIdx.x < st) {
            r1[threadIdx.x] += r1[threadIdx.x + st];
            r2[threadIdx.x] += r2[threadIdx.x + st];
        }
        __syncthreads();
    }
    float scale = r1[0] + g_wbar[DD];
    float inv = rsqrtf(scale * scale * r2[0] / DD + 1e-5f);
    for (int d = threadIdx.x; d < DD; d += 256) {
        float hv = hr[d] * scale;
        hr[d] = hv;
        split_store(hv * inv * w[d], g_ah, g_al, (size_t)row * DD + d);
    }
}

// ------------------- fused rw-scale + layernorm -> fp16 -------------------
__global__ void k_rw_ln(const float* __restrict__ gam, const float* __restrict__ bet) {
    int row = blockIdx.x;
    const float* hr = g_h + (size_t)row * DD;
    __half* outp = (__half*)g_ah;
    float dot = 0.f, ss = 0.f, sum = 0.f;
    for (int d = threadIdx.x; d < DD; d += 256) {
        float v = hr[d];
        dot += v * g_wbar[d];
        ss += v * v;
        sum += v;
    }
    __shared__ float r1[256], r2[256], r3[256];
    r1[threadIdx.x] = dot; r2[threadIdx.x] = ss; r3[threadIdx.x] = sum; __syncthreads();
    for (int st = 128; st > 0; st >>= 1) {
        if (threadIdx.x < st) {
            r1[threadIdx.x] += r1[threadIdx.x + st];
            r2[threadIdx.x] += r2[threadIdx.x + st];
            r3[threadIdx.x] += r3[threadIdx.x + st];
        }
        __syncthreads();
    }
    float scale = r1[0] + g_wbar[DD];
    float mean = scale * r3[0] / DD;
    float var = scale * scale * r2[0] / DD - mean * mean;
    float inv = rsqrtf(var + 1e-5f);
    for (int d = threadIdx.x; d < DD; d += 256) {
        float hv = hr[d] * scale;
        outp[(size_t)row * DD + d] = __float2half((hv - mean) * inv * gam[d] + bet[d]);
    }
}

// ------------------- causal dwconv + silu -> u fp32 + split ---------------
__global__ void k_conv_split(const float* __restrict__ cw, const float* __restrict__ cb) {
    int idx = blockIdx.x * 256 + threadIdx.x;
    if (idx >= MROWS * EE) return;
    int row = idx >> 11;
    int e = idx & (EE - 1);
    int b = row >> 10;
    int l = row & 1023;
    float acc = cb[e];
    #pragma unroll
    for (int k = 0; k < 4; k++) {
        int l2 = l - 3 + k;
        if (l2 >= 0)
            acc += g_uz[(size_t)(b * LL + l2) * (2 * EE) + e] * cw[e * 4 + k];
    }
    float u = siluf(acc);
    g_u[idx] = u;
    split_store(u, g_ah, g_al, idx);
}

// ------------------- selective scan (integer-power fast path) -------------
__global__ void k_scanA2(const float* __restrict__ A_log_l) {
    int c = blockIdx.x, eg = blockIdx.y, b = blockIdx.z;
    int e = eg * 128 + threadIdx.x;
    __shared__ float sB[CLEN * 16];
    for (int i = threadIdx.x; i < CLEN * 16; i += 128) {
        int tl = i >> 4, j = i & 15;
        sB[i] = g_dbc[(size_t)(b * LL + c * CLEN + tl) * DBCW + RR + j];
    }
    __syncthreads();
    float cs[SS];
    bool consec = true;
    #pragma unroll
    for (int s = 0; s < SS; s++) {
        cs[s] = __expf(A_log_l[e * SS + s]);
        consec = consec && (fabsf(cs[s] - (float)(s + 1)) < 1e-4f);
    }
    float h[SS];
    #pragma unroll
    for (int s = 0; s < SS; s++) h[s] = 0.f;
    float dsum = 0.f;
    int rowbase = b * LL + c * CLEN;
    if (consec) {
        for (int tl = 0; tl < CLEN; tl++) {
            size_t off = (size_t)(rowbase + tl) * EE + e;
            float dv = g_delta[off];
            float du = dv * g_u[off];
            dsum += dv;
            float q = __expf(-dv), p = 1.f;
            #pragma unroll
            for (int s = 0; s < SS; s++) {
                p *= q;
                h[s] = fmaf(p, h[s], du * sB[tl * 16 + s]);
            }
        }
    } else {
        for (int tl = 0; tl < CLEN; tl++) {
            size_t off = (size_t)(rowbase + tl) * EE + e;
            float dv = g_delta[off];
            float du = dv * g_u[off];
            dsum += dv;
            #pragma unroll
            for (int s = 0; s < SS; s++) {
                float dA = __expf(-dv * cs[s]);
                h[s] = fmaf(dA, h[s], du * sB[tl * 16 + s]);
            }
        }
    }
    float P[SS];
    if (consec) {
        float Q = __expf(-dsum), p = 1.f;
        #pragma unroll
        for (int s = 0; s < SS; s++) { p *= Q; P[s] = p; }
    } else {
        #pragma unroll
        for (int s = 0; s < SS; s++) P[s] = __expf(-dsum * cs[s]);
    }
    size_t base = ((size_t)c * BB * EE + b * EE + e) * SS;
    float4* Pp = (float4*)(g_P + base);
    float4* Hp = (float4*)(g_hend + base);
    #pragma unroll
    for (int q = 0; q < 4; q++) {
        Pp[q] = make_float4(P[q*4], P[q*4+1], P[q*4+2], P[q*4+3]);
        Hp[q] = make_float4(h[q*4], h[q*4+1], h[q*4+2], h[q*4+3]);
    }
}

__global__ void k_scanB() {
    int idx = blockIdx.x * 256 + threadIdx.x;
    if (idx >= BB * EE) return;
    float h[SS];
    #pragma unroll
    for (int s = 0; s < SS; s++) h[s] = 0.f;
    for (int c = 0; c < NCHUNK; c++) {
        size_t base = ((size_t)c * BB * EE + idx) * SS;
        float4* H0 = (float4*)(g_h0c + base);
        const float4* Pp = (const float4*)(g_P + base);
        const float4* He = (const float4*)(g_hend + base);
        #pragma unroll
        for (int q = 0; q < 4; q++) {
            H0[q] = make_float4(h[q*4], h[q*4+1], h[q*4+2], h[q*4+3]);
            float4 p = Pp[q], he = He[q];
            h[q*4+0] = fmaf(p.x, h[q*4+0], he.x);
            h[q*4+1] = fmaf(p.y, h[q*4+1], he.y);
            h[q*4+2] = fmaf(p.z, h[q*4+2], he.z);
            h[q*4+3] = fmaf(p.w, h[q*4+3], he.w);
        }
    }
}

// scanC fused with gate: writes gate = (y + u*Dsk) * silu(z) as bf16 split
__global__ void k_scanC2(const float* __restrict__ A_log_l, const float* __restrict__ Dsk) {
    int c = blockIdx.x, eg = blockIdx.y, b = blockIdx.z;
    int e = eg * 128 + threadIdx.x;
    __shared__ float sBC[CLEN * 32];
    for (int i = threadIdx.x; i < CLEN * 32; i += 128) {
        int tl = i >> 5, j = i & 31;
        sBC[i] = g_dbc[(size_t)(b * LL + c * CLEN + tl) * DBCW + RR + j];
    }
    __syncthreads();
    float cs[SS];
    bool consec = true;
    #pragma unroll
    for (int s = 0; s < SS; s++) {
        cs[s] = __expf(A_log_l[e * SS + s]);
        consec = consec && (fabsf(cs[s] - (float)(s + 1)) < 1e-4f);
    }
    float h[SS];
    size_t base = ((size_t)c * BB * EE + b * EE + e) * SS;
    #pragma unroll
    for (int q = 0; q < 4; q++) {
        float4 v = ((const float4*)(g_h0c + base))[q];
        h[q*4+0] = v.x; h[q*4+1] = v.y; h[q*4+2] = v.z; h[q*4+3] = v.w;
    }
    float dsk = Dsk[e];
    int rowbase = b * LL + c * CLEN;
    if (consec) {
        for (int tl = 0; tl < CLEN; tl++) {
            size_t off = (size_t)(rowbase + tl) * EE + e;
            float dv = g_delta[off];
            float uv = g_u[off];
            float du = dv * uv;
            float q = __expf(-dv), p = 1.f, y = 0.f;
            #pragma unroll
            for (int s = 0; s < SS; s++) {
                p *= q;
                h[s] = fmaf(p, h[s], du * sBC[tl * 32 + s]);
                y = fmaf(h[s], sBC[tl * 32 + 16 + s], y);
            }
            float yv = y + uv * dsk;
            float z = g_uz[(size_t)(rowbase + tl) * (2 * EE) + EE + e];
            split_store(yv * siluf(z), g_ah, g_al, off);
        }
    } else {
        for (int tl = 0; tl < CLEN; tl++) {
            size_t off = (size_t)(rowbase + tl) * EE + e;
            float dv = g_delta[off];
            float uv = g_u[off];
            float du = dv * uv;
            float y = 0.f;
            #pragma unroll
            for (int s = 0; s < SS; s++) {
                float dA = __expf(-dv * cs[s]);
                h[s] = fmaf(dA, h[s], du * sBC[tl * 32 + s]);
                y = fmaf(h[s], sBC[tl * 32 + 16 + s], y);
            }
            float yv = y + uv * dsk;
            float z = g_uz[(size_t)(rowbase + tl) * (2 * EE) + EE + e];
            split_store(yv * siluf(z), g_ah, g_al, off);
        }
    }
}

// ------------------- wbar = mean_s W_rw + mean b_rw -----------------------
__global__ void k_wbar(const float* __restrict__ W_rw_l, const float* __restrict__ b_rw_l) {
    int d = blockIdx.x * 256 + threadIdx.x;
    if (d < DD) {
        float s = 0.f;
        #pragma unroll
        for (int j = 0; j < SS; j++) s += W_rw_l[d * SS + j];
        g_wbar[d] = s * (1.f / SS);
    }
    if (blockIdx.x == 0 && threadIdx.x == 0) {
        float bb = 0.f;
        #pragma unroll
        for (int s = 0; s < SS; s++) bb += b_rw_l[s];
        g_wbar[DD] = bb * (1.f / SS);
    }
}

// ------------------- launch -----------------------------------------------
extern "C" void kernel_launch(void* const* d_in, const int* in_sizes, int n_in,
                              void* d_out, int out_size) {
    const int*   x      = (const int*)d_in[0];
    const float* mask   = (const float*)d_in[1];
    const float* emb    = (const float*)d_in[2];
    const float* norm_w = (const float*)d_in[3];
    const float* W_in   = (const float*)d_in[4];
    const float* conv_w = (const float*)d_in[5];
    const float* conv_b = (const float*)d_in[6];
    const float* W_x    = (const float*)d_in[7];
    const float* W_dt   = (const float*)d_in[8];
    const float* b_dt   = (const float*)d_in[9];
    const float* A_log  = (const float*)d_in[10];
    const float* D_skip = (const float*)d_in[11];
    const float* W_out  = (const float*)d_in[12];
    const float* W_rw   = (const float*)d_in[13];
    const float* b_rw   = (const float*)d_in[14];
    const float* ln_g   = (const float*)d_in[15];
    const float* ln_b   = (const float*)d_in[16];
    const float* head_W = (const float*)d_in[17];
    float* out = (float*)d_out;

    float *ph, *puz, *pdbc, *pdelta;
    __nv_bfloat16 *pah, *pal, *pbh, *pbl;
    cudaGetSymbolAddress((void**)&ph,     g_h);
    cudaGetSymbolAddress((void**)&puz,    g_uz);
    cudaGetSymbolAddress((void**)&pdbc,   g_dbc);
    cudaGetSymbolAddress((void**)&pdelta, g_delta);
    cudaGetSymbolAddress((void**)&pah,    g_ah);
    cudaGetSymbolAddress((void**)&pal,    g_al);
    cudaGetSymbolAddress((void**)&pbh,    g_bh);
    cudaGetSymbolAddress((void**)&pbl,    g_bl);

    cudaFuncSetAttribute(tc_gemm<0>, cudaFuncAttributeMaxDynamicSharedMemorySize, TG_SMEM);
    cudaFuncSetAttribute(tc_gemm<1>, cudaFuncAttributeMaxDynamicSharedMemorySize, TG_SMEM);
    cudaFuncSetAttribute(tc_gemm<2>, cudaFuncAttributeMaxDynamicSharedMemorySize, TG_SMEM);
    cudaFuncSetAttribute(tc_gemm<3>, cudaFuncAttributeMaxDynamicSharedMemorySize, TG_SMEM);
    cudaFuncSetAttribute(tc_gemm1,   cudaFuncAttributeMaxDynamicSharedMemorySize, TG1_SMEM);

    dim3 cvtb(32, 8);

    k_embed<<<(MROWS * DD + 255) / 256, 256>>>(x, mask, emb);

    for (int l = 0; l < NLAYER; l++) {
        if (l == 0)
            k_rms_split<<<MROWS, 256>>>(norm_w);
        else
            k_rw_rms<<<MROWS, 256>>>(norm_w + l * DD);   // applies prev layer's rw too

        // uz = xn @ W_in   (2048x1024 @ 1024x4096)
        k_cvt_wT<<<dim3((2 * EE + 31) / 32, (DD + 31) / 32), cvtb>>>(
            W_in + (size_t)l * DD * 2 * EE, DD, 2 * EE, pbh, pbl);
        tc_gemm<0><<<dim3(MROWS / 128, 2 * EE / 128, 1), 256, TG_SMEM>>>(
            pah, pal, pbh, pbl, puz, 2 * EE, MROWS, 2 * EE, DD, nullptr);

        k_conv_split<<<(MROWS * EE + 255) / 256, 256>>>(conv_w + l * EE * 4, conv_b + l * EE);

        // dbc = u @ W_x   (split-K 8, atomic accumulate)
        k_cvt_wT<<<dim3((DBCW + 31) / 32, (EE + 31) / 32), cvtb>>>(
            W_x + (size_t)l * EE * DBCW, EE, DBCW, pbh, pbl);
        k_zero<<<(MROWS * DBCW + 255) / 256, 256>>>(pdbc, MROWS * DBCW);
        tc_gemm<3><<<dim3(MROWS / 128, 1, 8), 256, TG_SMEM>>>(
            pah, pal, pbh, pbl, pdbc, DBCW, MROWS, DBCW, EE, nullptr);

        // delta = softplus(dr @ W_dt + b_dt)
        k_cvt_act<<<(MROWS * RR + 255) / 256, 256>>>(pdbc, MROWS, RR, DBCW, pah, pal);
        k_cvt_wT<<<dim3((EE + 31) / 32, (RR + 31) / 32), cvtb>>>(
            W_dt + (size_t)l * RR * EE, RR, EE, pbh, pbl);
        tc_gemm<2><<<dim3(MROWS / 128, EE / 128, 1), 256, TG_SMEM>>>(
            pah, pal, pbh, pbl, pdelta, EE, MROWS, EE, RR, b_dt + l * EE);

        k_scanA2<<<dim3(NCHUNK, EE / 128, BB), 128>>>(A_log + (size_t)l * EE * SS);
        k_scanB<<<(BB * EE + 255) / 256, 256>>>();
        k_scanC2<<<dim3(NCHUNK, EE / 128, BB), 128>>>(A_log + (size_t)l * EE * SS,
                                                      D_skip + l * EE);

        // h += gate @ W_out
        k_cvt_wT<<<dim3((DD + 31) / 32, (EE + 31) / 32), cvtb>>>(
            W_out + (size_t)l * EE * DD, EE, DD, pbh, pbl);
        tc_gemm<1><<<dim3(MROWS / 128, DD / 128, 1), 256, TG_SMEM>>>(
            pah, pal, pbh, pbl, ph, DD, MROWS, DD, EE, nullptr);

        k_wbar<<<(DD + 255) / 256, 256>>>(W_rw + (size_t)l * DD * SS, b_rw + l * SS);
    }

    k_rw_ln<<<MROWS, 256>>>(ln_g, ln_b);   // writes fp16 into g_ah

    // logits = xn @ head_W  (2048x1024 @ 1024x32000), fp16 single-pass
    k_cvt_wT_f16<<<dim3((VV + 31) / 32, (DD + 31) / 32), cvtb>>>(head_W, DD, VV, (__half*)pbh);
    tc_gemm1<<<dim3(MROWS / 128, VV / 128, 1), 256, TG1_SMEM>>>(
        (const __half*)pah, (const __half*)pbh, out, VV, MROWS, VV, DD);
}

// round 10
// speedup vs baseline: 5.5867x; 1.0399x over previous
#include <cuda_runtime.h>
#include <cuda_bf16.h>
#include <cuda_fp16.h>
#include <math.h>
#include <stdint.h>

#define BB 2
#define LL 1024
#define DD 1024
#define EE 2048
#define SS 16
#define RR 64
#define NLAYER 4
#define VV 32000
#define MROWS (BB*LL)
#define NCHUNK 16
#define CLEN (LL/NCHUNK)
#define DBCW 96

// ------------------- scratch (static device globals, no allocs) -------------
__device__ float g_h[MROWS*DD];
__device__ float g_uz[MROWS*2*EE];
__device__ float g_u[MROWS*EE];
__device__ float g_dbc[MROWS*DBCW];
__device__ float g_delta[MROWS*EE];
__device__ float g_P[NCHUNK*BB*EE*SS];
__device__ float g_hend[NCHUNK*BB*EE*SS];
__device__ float g_h0c[NCHUNK*BB*EE*SS];
__device__ float g_wbar[DD+1];

// bf16 hi/lo split operand buffers (16-byte aligned); g_ah/g_bh reused as fp16
__device__ __align__(16) __nv_bfloat16 g_ah[MROWS*EE];
__device__ __align__(16) __nv_bfloat16 g_al[MROWS*EE];
__device__ __align__(16) __nv_bfloat16 g_bh[(size_t)VV*DD];
__device__ __align__(16) __nv_bfloat16 g_bl[(size_t)VV*DD];

__device__ __forceinline__ float siluf(float x) { return x / (1.f + __expf(-x)); }
__device__ __forceinline__ float softplusf(float x) {
    return (x > 20.f) ? x : log1pf(__expf(x));
}
__device__ __forceinline__ void split_store(float x, __nv_bfloat16* h, __nv_bfloat16* l,
                                            size_t idx) {
    __nv_bfloat16 hh = __float2bfloat16(x);
    h[idx] = hh;
    l[idx] = __float2bfloat16(x - __bfloat162float(hh));
}

// ------------------- conversions ------------------------------------------
__global__ void k_cvt_act(const float* __restrict__ A, int M, int K, int lda,
                          __nv_bfloat16* __restrict__ h, __nv_bfloat16* __restrict__ l) {
    int idx = blockIdx.x * 256 + threadIdx.x;
    if (idx >= M * K) return;
    int r = idx / K, c = idx - r * K;
    split_store(A[(size_t)r * lda + c], h, l, idx);
}

// weights: fp32 [K,N] row-major -> transposed bf16 hi/lo [N,K]
__global__ void k_cvt_wT(const float* __restrict__ W, int K, int N,
                         __nv_bfloat16* __restrict__ th, __nv_bfloat16* __restrict__ tl) {
    __shared__ float t[32][33];
    int n0 = blockIdx.x * 32, k0 = blockIdx.y * 32;
    int tx = threadIdx.x, ty = threadIdx.y;
    #pragma unroll
    for (int j = 0; j < 32; j += 8) {
        int k = k0 + ty + j, n = n0 + tx;
        t[ty + j][tx] = (k < K && n < N) ? W[(size_t)k * N + n] : 0.f;
    }
    __syncthreads();
    #pragma unroll
    for (int j = 0; j < 32; j += 8) {
        int n = n0 + ty + j, k = k0 + tx;
        if (n < N && k < K)
            split_store(t[tx][ty + j], th, tl, (size_t)n * K + k);
    }
}

// weights: fp32 [K,N] -> transposed fp16 [N,K] (head only)
__global__ void k_cvt_wT_f16(const float* __restrict__ W, int K, int N,
                             __half* __restrict__ th) {
    __shared__ float t[32][33];
    int n0 = blockIdx.x * 32, k0 = blockIdx.y * 32;
    int tx = threadIdx.x, ty = threadIdx.y;
    #pragma unroll
    for (int j = 0; j < 32; j += 8) {
        int k = k0 + ty + j, n = n0 + tx;
        t[ty + j][tx] = (k < K && n < N) ? W[(size_t)k * N + n] : 0.f;
    }
    __syncthreads();
    #pragma unroll
    for (int j = 0; j < 32; j += 8) {
        int n = n0 + ty + j, k = k0 + tx;
        if (n < N && k < K)
            th[(size_t)n * K + k] = __float2half(t[tx][ty + j]);
    }
}

__global__ void k_zero(float* p, int n) {
    int idx = blockIdx.x * 256 + threadIdx.x;
    if (idx < n) p[idx] = 0.f;
}

// ------------------- GEMM common ------------------------------------------
__device__ __forceinline__ uint32_t smem_u32(const void* p) {
    uint32_t a;
    asm("{ .reg .u64 t; cvta.to.shared.u64 t, %1; cvt.u32.u64 %0, t; }" : "=r"(a) : "l"(p));
    return a;
}
__device__ __forceinline__ void cpa16(uint32_t s, const void* g, bool v) {
    asm volatile("cp.async.cg.shared.global [%0], [%1], 16, %2;"
                 :: "r"(s), "l"(g), "r"(v ? 16 : 0));
}
__device__ __forceinline__ uint32_t swz128(int row, int kb) {
    return (uint32_t)(row * 128 + ((((kb >> 4) ^ (row & 7))) << 4) + (kb & 15));
}
#define LDMX4(r, ad) \
    asm volatile("ldmatrix.sync.aligned.m8n8.x4.shared.b16 {%0,%1,%2,%3}, [%4];" \
                 : "=r"((r)[0]), "=r"((r)[1]), "=r"((r)[2]), "=r"((r)[3]) : "r"(ad))
#define MMA16(d, a, b) \
    asm volatile("mma.sync.aligned.m16n8k16.row.col.f32.bf16.bf16.f32 " \
                 "{%0,%1,%2,%3},{%4,%5,%6,%7},{%8,%9},{%0,%1,%2,%3};" \
                 : "+f"((d)[0]), "+f"((d)[1]), "+f"((d)[2]), "+f"((d)[3]) \
                 : "r"((a)[0]), "r"((a)[1]), "r"((a)[2]), "r"((a)[3]), \
                   "r"((b)[0]), "r"((b)[1]))
#define MMA16H(d, a, b) \
    asm volatile("mma.sync.aligned.m16n8k16.row.col.f32.f16.f16.f32 " \
                 "{%0,%1,%2,%3},{%4,%5,%6,%7},{%8,%9},{%0,%1,%2,%3};" \
                 : "+f"((d)[0]), "+f"((d)[1]), "+f"((d)[2]), "+f"((d)[3]) \
                 : "r"((a)[0]), "r"((a)[1]), "r"((a)[2]), "r"((a)[3]), \
                   "r"((b)[0]), "r"((b)[1]))

// ------------------- bf16-split 3-pass GEMM (internal layers) -------------
// Tile 128(M) x 64(N) x 64(K); 2-stage pipeline; 2 CTAs/SM.
// Stage: AH 16KB | AL 16KB | BH 8KB | BL 8KB = 48KB
#define TG_SMEM (2 * 49152)
#define T_AL 16384
#define T_BH 32768
#define T_BL 40960

// MODE: 0 store, 1 C+=AB, 2 softplus(AB+bias), 3 atomicAdd (split-K via blockIdx.z)
template<int MODE>
__global__ __launch_bounds__(256, 2)
void tc_gemm(const __nv_bfloat16* __restrict__ Ah, const __nv_bfloat16* __restrict__ Al,
             const __nv_bfloat16* __restrict__ Bh, const __nv_bfloat16* __restrict__ Bl,
             float* __restrict__ C, int ldc, int M, int N, int K,
             const float* __restrict__ bias)
{
    extern __shared__ char smem[];
    uint32_t sb = smem_u32(smem);
    int tid = threadIdx.x, lane = tid & 31, warp = tid >> 5;
    int wm = warp & 1, wn = warp >> 1;     // 2 x 64 rows, 4 x 16 cols
    int bm = blockIdx.x * 128, bn = blockIdx.y * 64;
    int kn = K / gridDim.z;
    int t0 = (blockIdx.z * kn) >> 6, tn = kn >> 6;

    float acc[4][2][4];
    #pragma unroll
    for (int i = 0; i < 4; i++)
        #pragma unroll
        for (int j = 0; j < 2; j++)
            #pragma unroll
            for (int q = 0; q < 4; q++) acc[i][j][q] = 0.f;

    auto load_stage = [&](int kt, int stg) {
        int k0 = kt << 6;
        uint32_t sbase = sb + stg * 49152;
        #pragma unroll
        for (int i = 0; i < 4; i++) {            // A: 128 rows x 8 chunks
            int idx = tid + i * 256;
            int row = idx >> 3, ch = idx & 7;
            uint32_t so = (uint32_t)(row * 128 + ((ch ^ (row & 7)) << 4));
            size_t ga = (size_t)(bm + row) * K + k0 + ch * 8;
            cpa16(sbase + so, Ah + ga, true);
            cpa16(sbase + T_AL + so, Al + ga, true);
        }
        #pragma unroll
        for (int i = 0; i < 2; i++) {            // B: 64 rows x 8 chunks
            int idx = tid + i * 256;
            int row = idx >> 3, ch = idx & 7;
            uint32_t so = (uint32_t)(row * 128 + ((ch ^ (row & 7)) << 4));
            bool bv = (bn + row) < N;
            size_t gb = bv ? ((size_t)(bn + row) * K + k0 + ch * 8) : 0;
            cpa16(sbase + T_BH + so, Bh + gb, bv);
            cpa16(sbase + T_BL + so, Bl + gb, bv);
        }
        asm volatile("cp.async.commit_group;");
    };

    load_stage(t0, 0);

    for (int i = 0; i < tn; i++) {
        if (i + 1 < tn) load_stage(t0 + i + 1, (i + 1) & 1);
        else asm volatile("cp.async.commit_group;");
        asm volatile("cp.async.wait_group 1;");
        __syncthreads();

        uint32_t base = sb + (i & 1) * 49152;
        #pragma unroll
        for (int ks = 0; ks < 4; ks++) {
            uint32_t ahf[4][4], alf[4][4], bhf[4], blf[4];
            #pragma unroll
            for (int ii = 0; ii < 4; ii++) {
                int row = wm * 64 + ii * 16 + (lane & 15);
                int kb = ks * 32 + ((lane >> 4) << 4);
                uint32_t off = swz128(row, kb);
                LDMX4(ahf[ii], base + off);
                LDMX4(alf[ii], base + T_AL + off);
            }
            {
                int g = lane >> 3, rr = lane & 7;
                int n = wn * 16 + ((g >> 1) << 3) + rr;
                int kb = ks * 32 + ((g & 1) << 4);
                uint32_t off = swz128(n, kb);
                LDMX4(bhf, base + T_BH + off);
                LDMX4(blf, base + T_BL + off);
            }
            #pragma unroll
            for (int ii = 0; ii < 4; ii++)
                #pragma unroll
                for (int j = 0; j < 2; j++) {
                    uint32_t* bhp = &bhf[j * 2];
                    uint32_t* blp = &blf[j * 2];
                    MMA16(acc[ii][j], ahf[ii], bhp);
                    MMA16(acc[ii][j], ahf[ii], blp);
                    MMA16(acc[ii][j], alf[ii], bhp);
                }
        }
        __syncthreads();
    }

    #pragma unroll
    for (int i = 0; i < 4; i++) {
        int r0 = bm + wm * 64 + i * 16 + (lane >> 2);
        #pragma unroll
        for (int j = 0; j < 2; j++) {
            int c = bn + wn * 16 + j * 8 + (lane & 3) * 2;
            if (c >= N) continue;
            #pragma unroll
            for (int half = 0; half < 2; half++) {
                int r = r0 + half * 8;
                float v0 = acc[i][j][half * 2], v1 = acc[i][j][half * 2 + 1];
                float* cp = C + (size_t)r * ldc + c;
                if (MODE == 3) {
                    atomicAdd(cp, v0); atomicAdd(cp + 1, v1);
                } else {
                    if (MODE == 1) {
                        float2 old = *(float2*)cp;
                        v0 += old.x; v1 += old.y;
                    } else if (MODE == 2) {
                        v0 = softplusf(v0 + bias[c]);
                        v1 = softplusf(v1 + bias[c + 1]);
                    }
                    *(float2*)cp = make_float2(v0, v1);
                }
            }
        }
    }
}

// ------------------- fp16 single-pass GEMM (head) -------------------------
// 96KB smem (3 stages x 32KB), 2 CTAs/SM
#define TG1_SMEM (3 * 32768)
__global__ __launch_bounds__(256, 2)
void tc_gemm1(const __half* __restrict__ A, const __half* __restrict__ Bp,
              float* __restrict__ C, int ldc, int M, int N, int K)
{
    extern __shared__ char smem[];
    uint32_t sb = smem_u32(smem);
    int tid = threadIdx.x, lane = tid & 31, warp = tid >> 5;
    int wm = warp & 1, wn = warp >> 1;
    int bm = blockIdx.x * 128, bn = blockIdx.y * 128;
    int tn = K >> 6;

    float acc[4][4][4];
    #pragma unroll
    for (int i = 0; i < 4; i++)
        #pragma unroll
        for (int j = 0; j < 4; j++)
            #pragma unroll
            for (int q = 0; q < 4; q++) acc[i][j][q] = 0.f;

    auto load_stage = [&](int kt, int stg) {
        int k0 = kt << 6;
        uint32_t sbase = sb + stg * 32768;
        #pragma unroll
        for (int i = 0; i < 4; i++) {
            int idx = tid + i * 256;
            int half_sel = idx >> 9;
            int sub = idx & 511;
            int row = sub >> 2, ch = (sub & 3) << 1;
            uint32_t so = (uint32_t)(row * 128 + ((ch ^ (row & 7)) << 4));
            uint32_t so2 = (uint32_t)(row * 128 + (((ch + 1) ^ (row & 7)) << 4));
            if (half_sel == 0) {
                size_t ga = (size_t)(bm + row) * K + k0 + ch * 8;
                cpa16(sbase + so, A + ga, true);
                cpa16(sbase + so2, A + ga + 8, true);
            } else {
                bool bv = (bn + row) < N;
                size_t gb = bv ? ((size_t)(bn + row) * K + k0 + ch * 8) : 0;
                cpa16(sbase + 16384 + so, Bp + gb, bv);
                cpa16(sbase + 16384 + so2, Bp + gb + 8, bv);
            }
        }
        asm volatile("cp.async.commit_group;");
    };

    load_stage(0, 0);
    if (tn > 1) load_stage(1, 1);
    else asm volatile("cp.async.commit_group;");

    for (int i = 0; i < tn; i++) {
        asm volatile("cp.async.wait_group 1;");
        __syncthreads();
        if (i + 2 < tn) load_stage(i + 2, (i + 2) % 3);
        else asm volatile("cp.async.commit_group;");

        uint32_t base = sb + (i % 3) * 32768;
        #pragma unroll
        for (int ks = 0; ks < 4; ks++) {
            uint32_t af[4][4], bf[2][4];
            #pragma unroll
            for (int ii = 0; ii < 4; ii++) {
                int row = wm * 64 + ii * 16 + (lane & 15);
                int kb = ks * 32 + ((lane >> 4) << 4);
                LDMX4(af[ii], base + swz128(row, kb));
            }
            #pragma unroll
            for (int jj = 0; jj < 2; jj++) {
                int g = lane >> 3, rr = lane & 7;
                int n = wn * 32 + jj * 16 + ((g >> 1) << 3) + rr;
                int kb = ks * 32 + ((g & 1) << 4);
                LDMX4(bf[jj], base + 16384 + swz128(n, kb));
            }
            #pragma unroll
            for (int ii = 0; ii < 4; ii++)
                #pragma unroll
                for (int j = 0; j < 4; j++)
                    MMA16H(acc[ii][j], af[ii], &bf[j >> 1][(j & 1) * 2]);
        }
    }

    #pragma unroll
    for (int i = 0; i < 4; i++) {
        int r0 = bm + wm * 64 + i * 16 + (lane >> 2);
        #pragma unroll
        for (int j = 0; j < 4; j++) {
            int c = bn + wn * 32 + j * 8 + (lane & 3) * 2;
            if (c >= N) continue;
            #pragma unroll
            for (int half = 0; half < 2; half++) {
                int r = r0 + half * 8;
                *(float2*)(C + (size_t)r * ldc + c) =
                    make_float2(acc[i][j][half * 2], acc[i][j][half * 2 + 1]);
            }
        }
    }
}

// ------------------- embed ------------------------------------------------
__global__ void k_embed(const int* __restrict__ x, const float* __restrict__ mask,
                        const float* __restrict__ emb) {
    int idx = blockIdx.x * 256 + threadIdx.x;
    if (idx >= MROWS * DD) return;
    int row = idx >> 10;
    int d = idx & 1023;
    g_h[idx] = emb[(size_t)x[row] * DD + d] * mask[row];
}

// ------------------- rmsnorm (layer 0) -> split bf16 ----------------------
__global__ void k_rms_split(const float* __restrict__ w) {
    int row = blockIdx.x;
    const float* hr = g_h + (size_t)row * DD;
    float ss = 0.f;
    for (int d = threadIdx.x; d < DD; d += 256) { float v = hr[d]; ss += v * v; }
    __shared__ float red[256];
    red[threadIdx.x] = ss; __syncthreads();
    for (int st = 128; st > 0; st >>= 1) {
        if (threadIdx.x < st) red[threadIdx.x] += red[threadIdx.x + st];
        __syncthreads();
    }
    float scale = rsqrtf(red[0] / DD + 1e-5f);
    for (int d = threadIdx.x; d < DD; d += 256)
        split_store(hr[d] * scale * w[d], g_ah, g_al, (size_t)row * DD + d);
}

// ------------------- fused rw-scale + rmsnorm -> split --------------------
__global__ void k_rw_rms(const float* __restrict__ w) {
    int row = blockIdx.x;
    float* hr = g_h + (size_t)row * DD;
    float dot = 0.f, ss = 0.f;
    for (int d = threadIdx.x; d < DD; d += 256) {
        float v = hr[d];
        dot += v * g_wbar[d];
        ss += v * v;
    }
    __shared__ float r1[256], r2[256];
    r1[threadIdx.x] = dot; r2[threadIdx.x] = ss; __syncthreads();
    for (int st = 128; st > 0; st >>= 1) {
        if (threadIdx.x < st) {
            r1[threadIdx.x] += r1[threadIdx.x + st];
            r2[threadIdx.x] += r2[threadIdx.x + st];
        }
        __syncthreads();
    }
    float scale = r1[0] + g_wbar[DD];
    float inv = rsqrtf(scale * scale * r2[0] / DD + 1e-5f);
    for (int d = threadIdx.x; d < DD; d += 256) {
        float hv = hr[d] * scale;
        hr[d] = hv;
        split_store(hv * inv * w[d], g_ah, g_al, (size_t)row * DD + d);
    }
}

// ------------------- fused rw-scale + layernorm -> fp16 -------------------
__global__ void k_rw_ln(const float* __restrict__ gam, const float* __restrict__ bet) {
    int row = blockIdx.x;
    const float* hr = g_h + (size_t)row * DD;
    __half* outp = (__half*)g_ah;
    float dot = 0.f, ss = 0.f, sum = 0.f;
    for (int d = threadIdx.x; d < DD; d += 256) {
        float v = hr[d];
        dot += v * g_wbar[d];
        ss += v * v;
        sum += v;
    }
    __shared__ float r1[256], r2[256], r3[256];
    r1[threadIdx.x] = dot; r2[threadIdx.x] = ss; r3[threadIdx.x] = sum; __syncthreads();
    for (int st = 128; st > 0; st >>= 1) {
        if (threadIdx.x < st) {
            r1[threadIdx.x] += r1[threadIdx.x + st];
            r2[threadIdx.x] += r2[threadIdx.x + st];
            r3[threadIdx.x] += r3[threadIdx.x + st];
        }
        __syncthreads();
    }
    float scale = r1[0] + g_wbar[DD];
    float mean = scale * r3[0] / DD;
    float var = scale * scale * r2[0] / DD - mean * mean;
    float inv = rsqrtf(var + 1e-5f);
    for (int d = threadIdx.x; d < DD; d += 256) {
        float hv = hr[d] * scale;
        outp[(size_t)row * DD + d] = __float2half((hv - mean) * inv * gam[d] + bet[d]);
    }
}

// ------------------- causal dwconv + silu -> u fp32 + split ---------------
__global__ void k_conv_split(const float* __restrict__ cw, const float* __restrict__ cb) {
    int idx = blockIdx.x * 256 + threadIdx.x;
    if (idx >= MROWS * EE) return;
    int row = idx >> 11;
    int e = idx & (EE - 1);
    int b = row >> 10;
    int l = row & 1023;
    float acc = cb[e];
    #pragma unroll
    for (int k = 0; k < 4; k++) {
        int l2 = l - 3 + k;
        if (l2 >= 0)
            acc += g_uz[(size_t)(b * LL + l2) * (2 * EE) + e] * cw[e * 4 + k];
    }
    float u = siluf(acc);
    g_u[idx] = u;
    split_store(u, g_ah, g_al, idx);
}

// ------------------- selective scan (integer-power fast path) -------------
__global__ void k_scanA2(const float* __restrict__ A_log_l) {
    int c = blockIdx.x, eg = blockIdx.y, b = blockIdx.z;
    int e = eg * 128 + threadIdx.x;
    __shared__ float sB[CLEN * 16];
    for (int i = threadIdx.x; i < CLEN * 16; i += 128) {
        int tl = i >> 4, j = i & 15;
        sB[i] = g_dbc[(size_t)(b * LL + c * CLEN + tl) * DBCW + RR + j];
    }
    __syncthreads();
    float cs[SS];
    bool consec = true;
    #pragma unroll
    for (int s = 0; s < SS; s++) {
        cs[s] = __expf(A_log_l[e * SS + s]);
        consec = consec && (fabsf(cs[s] - (float)(s + 1)) < 1e-4f);
    }
    float h[SS];
    #pragma unroll
    for (int s = 0; s < SS; s++) h[s] = 0.f;
    float dsum = 0.f;
    int rowbase = b * LL + c * CLEN;
    if (consec) {
        for (int tl = 0; tl < CLEN; tl++) {
            size_t off = (size_t)(rowbase + tl) * EE + e;
            float dv = g_delta[off];
            float du = dv * g_u[off];
            dsum += dv;
            float q = __expf(-dv), p = 1.f;
            #pragma unroll
            for (int s = 0; s < SS; s++) {
                p *= q;
                h[s] = fmaf(p, h[s], du * sB[tl * 16 + s]);
            }
        }
    } else {
        for (int tl = 0; tl < CLEN; tl++) {
            size_t off = (size_t)(rowbase + tl) * EE + e;
            float dv = g_delta[off];
            float du = dv * g_u[off];
            dsum += dv;
            #pragma unroll
            for (int s = 0; s < SS; s++) {
                float dA = __expf(-dv * cs[s]);
                h[s] = fmaf(dA, h[s], du * sB[tl * 16 + s]);
            }
        }
    }
    float P[SS];
    if (consec) {
        float Q = __expf(-dsum), p = 1.f;
        #pragma unroll
        for (int s = 0; s < SS; s++) { p *= Q; P[s] = p; }
    } else {
        #pragma unroll
        for (int s = 0; s < SS; s++) P[s] = __expf(-dsum * cs[s]);
    }
    size_t base = ((size_t)c * BB * EE + b * EE + e) * SS;
    float4* Pp = (float4*)(g_P + base);
    float4* Hp = (float4*)(g_hend + base);
    #pragma unroll
    for (int q = 0; q < 4; q++) {
        Pp[q] = make_float4(P[q*4], P[q*4+1], P[q*4+2], P[q*4+3]);
        Hp[q] = make_float4(h[q*4], h[q*4+1], h[q*4+2], h[q*4+3]);
    }
}

__global__ void k_scanB() {
    int idx = blockIdx.x * 256 + threadIdx.x;
    if (idx >= BB * EE) return;
    float h[SS];
    #pragma unroll
    for (int s = 0; s < SS; s++) h[s] = 0.f;
    for (int c = 0; c < NCHUNK; c++) {
        size_t base = ((size_t)c * BB * EE + idx) * SS;
        float4* H0 = (float4*)(g_h0c + base);
        const float4* Pp = (const float4*)(g_P + base);
        const float4* He = (const float4*)(g_hend + base);
        #pragma unroll
        for (int q = 0; q < 4; q++) {
            H0[q] = make_float4(h[q*4], h[q*4+1], h[q*4+2], h[q*4+3]);
            float4 p = Pp[q], he = He[q];
            h[q*4+0] = fmaf(p.x, h[q*4+0], he.x);
            h[q*4+1] = fmaf(p.y, h[q*4+1], he.y);
            h[q*4+2] = fmaf(p.z, h[q*4+2], he.z);
            h[q*4+3] = fmaf(p.w, h[q*4+3], he.w);
        }
    }
}

// scanC fused with gate: writes gate = (y + u*Dsk) * silu(z) as bf16 split
__global__ void k_scanC2(const float* __restrict__ A_log_l, const float* __restrict__ Dsk) {
    int c = blockIdx.x, eg = blockIdx.y, b = blockIdx.z;
    int e = eg * 128 + threadIdx.x;
    __shared__ float sBC[CLEN * 32];
    for (int i = threadIdx.x; i < CLEN * 32; i += 128) {
        int tl = i >> 5, j = i & 31;
        sBC[i] = g_dbc[(size_t)(b * LL + c * CLEN + tl) * DBCW + RR + j];
    }
    __syncthreads();
    float cs[SS];
    bool consec = true;
    #pragma unroll
    for (int s = 0; s < SS; s++) {
        cs[s] = __expf(A_log_l[e * SS + s]);
        consec = consec && (fabsf(cs[s] - (float)(s + 1)) < 1e-4f);
    }
    float h[SS];
    size_t base = ((size_t)c * BB * EE + b * EE + e) * SS;
    #pragma unroll
    for (int q = 0; q < 4; q++) {
        float4 v = ((const float4*)(g_h0c + base))[q];
        h[q*4+0] = v.x; h[q*4+1] = v.y; h[q*4+2] = v.z; h[q*4+3] = v.w;
    }
    float dsk = Dsk[e];
    int rowbase = b * LL + c * CLEN;
    if (consec) {
        for (int tl = 0; tl < CLEN; tl++) {
            size_t off = (size_t)(rowbase + tl) * EE + e;
            float dv = g_delta[off];
            float uv = g_u[off];
            float du = dv * uv;
            float q = __expf(-dv), p = 1.f, y = 0.f;
            #pragma unroll
            for (int s = 0; s < SS; s++) {
                p *= q;
                h[s] = fmaf(p, h[s], du * sBC[tl * 32 + s]);
                y = fmaf(h[s], sBC[tl * 32 + 16 + s], y);
            }
            float yv = y + uv * dsk;
            float z = g_uz[(size_t)(rowbase + tl) * (2 * EE) + EE + e];
            split_store(yv * siluf(z), g_ah, g_al, off);
        }
    } else {
        for (int tl = 0; tl < CLEN; tl++) {
            size_t off = (size_t)(rowbase + tl) * EE + e;
            float dv = g_delta[off];
            float uv = g_u[off];
            float du = dv * uv;
            float y = 0.f;
            #pragma unroll
            for (int s = 0; s < SS; s++) {
                float dA = __expf(-dv * cs[s]);
                h[s] = fmaf(dA, h[s], du * sBC[tl * 32 + s]);
                y = fmaf(h[s], sBC[tl * 32 + 16 + s], y);
            }
            float yv = y + uv * dsk;
            float z = g_uz[(size_t)(rowbase + tl) * (2 * EE) + EE + e];
            split_store(yv * siluf(z), g_ah, g_al, off);
        }
    }
}

// ------------------- wbar = mean_s W_rw + mean b_rw -----------------------
__global__ void k_wbar(const float* __restrict__ W_rw_l, const float* __restrict__ b_rw_l) {
    int d = blockIdx.x * 256 + threadIdx.x;
    if (d < DD) {
        float s = 0.f;
        #pragma unroll
        for (int j = 0; j < SS; j++) s += W_rw_l[d * SS + j];
        g_wbar[d] = s * (1.f / SS);
    }
    if (blockIdx.x == 0 && threadIdx.x == 0) {
        float bb = 0.f;
        #pragma unroll
        for (int s = 0; s < SS; s++) bb += b_rw_l[s];
        g_wbar[DD] = bb * (1.f / SS);
    }
}

// ------------------- launch -----------------------------------------------
extern "C" void kernel_launch(void* const* d_in, const int* in_sizes, int n_in,
                              void* d_out, int out_size) {
    const int*   x      = (const int*)d_in[0];
    const float* mask   = (const float*)d_in[1];
    const float* emb    = (const float*)d_in[2];
    const float* norm_w = (const float*)d_in[3];
    const float* W_in   = (const float*)d_in[4];
    const float* conv_w = (const float*)d_in[5];
    const float* conv_b = (const float*)d_in[6];
    const float* W_x    = (const float*)d_in[7];
    const float* W_dt   = (const float*)d_in[8];
    const float* b_dt   = (const float*)d_in[9];
    const float* A_log  = (const float*)d_in[10];
    const float* D_skip = (const float*)d_in[11];
    const float* W_out  = (const float*)d_in[12];
    const float* W_rw   = (const float*)d_in[13];
    const float* b_rw   = (const float*)d_in[14];
    const float* ln_g   = (const float*)d_in[15];
    const float* ln_b   = (const float*)d_in[16];
    const float* head_W = (const float*)d_in[17];
    float* out = (float*)d_out;

    float *ph, *puz, *pdbc, *pdelta;
    __nv_bfloat16 *pah, *pal, *pbh, *pbl;
    cudaGetSymbolAddress((void**)&ph,     g_h);
    cudaGetSymbolAddress((void**)&puz,    g_uz);
    cudaGetSymbolAddress((void**)&pdbc,   g_dbc);
    cudaGetSymbolAddress((void**)&pdelta, g_delta);
    cudaGetSymbolAddress((void**)&pah,    g_ah);
    cudaGetSymbolAddress((void**)&pal,    g_al);
    cudaGetSymbolAddress((void**)&pbh,    g_bh);
    cudaGetSymbolAddress((void**)&pbl,    g_bl);

    cudaFuncSetAttribute(tc_gemm<0>, cudaFuncAttributeMaxDynamicSharedMemorySize, TG_SMEM);
    cudaFuncSetAttribute(tc_gemm<1>, cudaFuncAttributeMaxDynamicSharedMemorySize, TG_SMEM);
    cudaFuncSetAttribute(tc_gemm<2>, cudaFuncAttributeMaxDynamicSharedMemorySize, TG_SMEM);
    cudaFuncSetAttribute(tc_gemm<3>, cudaFuncAttributeMaxDynamicSharedMemorySize, TG_SMEM);
    cudaFuncSetAttribute(tc_gemm1,   cudaFuncAttributeMaxDynamicSharedMemorySize, TG1_SMEM);

    dim3 cvtb(32, 8);

    k_embed<<<(MROWS * DD + 255) / 256, 256>>>(x, mask, emb);

    for (int l = 0; l < NLAYER; l++) {
        if (l == 0)
            k_rms_split<<<MROWS, 256>>>(norm_w);
        else
            k_rw_rms<<<MROWS, 256>>>(norm_w + l * DD);   // applies prev layer's rw too

        // uz = xn @ W_in   (2048x1024 @ 1024x4096)
        k_cvt_wT<<<dim3((2 * EE + 31) / 32, (DD + 31) / 32), cvtb>>>(
            W_in + (size_t)l * DD * 2 * EE, DD, 2 * EE, pbh, pbl);
        tc_gemm<0><<<dim3(MROWS / 128, 2 * EE / 64, 1), 256, TG_SMEM>>>(
            pah, pal, pbh, pbl, puz, 2 * EE, MROWS, 2 * EE, DD, nullptr);

        k_conv_split<<<(MROWS * EE + 255) / 256, 256>>>(conv_w + l * EE * 4, conv_b + l * EE);

        // dbc = u @ W_x   (split-K 8, atomic accumulate)
        k_cvt_wT<<<dim3((DBCW + 31) / 32, (EE + 31) / 32), cvtb>>>(
            W_x + (size_t)l * EE * DBCW, EE, DBCW, pbh, pbl);
        k_zero<<<(MROWS * DBCW + 255) / 256, 256>>>(pdbc, MROWS * DBCW);
        tc_gemm<3><<<dim3(MROWS / 128, 2, 8), 256, TG_SMEM>>>(
            pah, pal, pbh, pbl, pdbc, DBCW, MROWS, DBCW, EE, nullptr);

        // delta = softplus(dr @ W_dt + b_dt)
        k_cvt_act<<<(MROWS * RR + 255) / 256, 256>>>(pdbc, MROWS, RR, DBCW, pah, pal);
        k_cvt_wT<<<dim3((EE + 31) / 32, (RR + 31) / 32), cvtb>>>(
            W_dt + (size_t)l * RR * EE, RR, EE, pbh, pbl);
        tc_gemm<2><<<dim3(MROWS / 128, EE / 64, 1), 256, TG_SMEM>>>(
            pah, pal, pbh, pbl, pdelta, EE, MROWS, EE, RR, b_dt + l * EE);

        k_scanA2<<<dim3(NCHUNK, EE / 128, BB), 128>>>(A_log + (size_t)l * EE * SS);
        k_scanB<<<(BB * EE + 255) / 256, 256>>>();
        k_scanC2<<<dim3(NCHUNK, EE / 128, BB), 128>>>(A_log + (size_t)l * EE * SS,
                                                      D_skip + l * EE);

        // h += gate @ W_out
        k_cvt_wT<<<dim3((DD + 31) / 32, (EE + 31) / 32), cvtb>>>(
            W_out + (size_t)l * EE * DD, EE, DD, pbh, pbl);
        tc_gemm<1><<<dim3(MROWS / 128, DD / 64, 1), 256, TG_SMEM>>>(
            pah, pal, pbh, pbl, ph, DD, MROWS, DD, EE, nullptr);

        k_wbar<<<(DD + 255) / 256, 256>>>(W_rw + (size_t)l * DD * SS, b_rw + l * SS);
    }

    k_rw_ln<<<MROWS, 256>>>(ln_g, ln_b);   // writes fp16 into g_ah

    // logits = xn @ head_W  (2048x1024 @ 1024x32000), fp16 single-pass
    k_cvt_wT_f16<<<dim3((VV + 31) / 32, (DD + 31) / 32), cvtb>>>(head_W, DD, VV, (__half*)pbh);
    tc_gemm1<<<dim3(MROWS / 128, VV / 128, 1), 256, TG1_SMEM>>>(
        (const __half*)pah, (const __half*)pbh, out, VV, MROWS, VV, DD);
}